// round 4
// baseline (speedup 1.0000x reference)
#include <cuda_runtime.h>
#include <cuda_bf16.h>
#include <cstdint>
#include <math.h>

// ---------------- problem constants ----------------
#define BATCH   32
#define LSEQ    16
#define BL      512
#define M1      25088        // BL * 49
#define C1      576
#define K1      768
#define DCNN    64
#define DRNN    256
#define G3      768
#define HORIZON 10

#define NFRM    (512*3*112*112)      // 19267584
#define K1P     2304                 // 3*768   [h|l|h] terms
#define K2P     15552                // 9*1728  per-tap [h|l|h]
#define NCH1    36                   // K1P/64
#define NCH2    243                  // K2P/64

// ---------------- helpers ----------------
__device__ __forceinline__ uint32_t smem_u32(const void* p) {
    uint32_t a;
    asm("{ .reg .u64 t; cvta.to.shared.u64 t, %1; cvt.u32.u64 %0, t; }" : "=r"(a) : "l"(p));
    return a;
}
#define SWZ(o) ((o) ^ (((o) >> 3) & 0x70))

#define CP16(dst, src) \
    asm volatile("cp.async.cg.shared.global [%0], [%1], 16;" :: "r"(dst), "l"(src))
#define CP_COMMIT() asm volatile("cp.async.commit_group;" ::: "memory")
#define CP_WAIT1()  asm volatile("cp.async.wait_group 1;" ::: "memory")
#define CP_WAIT0()  asm volatile("cp.async.wait_group 0;" ::: "memory")

__device__ __forceinline__ void ldsm_x4(uint32_t* r, uint32_t addr) {
    asm volatile("ldmatrix.sync.aligned.m8n8.x4.shared.b16 {%0,%1,%2,%3}, [%4];"
        : "=r"(r[0]), "=r"(r[1]), "=r"(r[2]), "=r"(r[3]) : "r"(addr));
}
__device__ __forceinline__ void ldsm_x2(uint32_t* r, uint32_t addr) {
    asm volatile("ldmatrix.sync.aligned.m8n8.x2.shared.b16 {%0,%1}, [%2];"
        : "=r"(r[0]), "=r"(r[1]) : "r"(addr));
}
__device__ __forceinline__ void mma16816(float* d, const uint32_t* a, const uint32_t* b) {
    asm volatile("mma.sync.aligned.m16n8k16.row.col.f32.bf16.bf16.f32 "
        "{%0,%1,%2,%3}, {%4,%5,%6,%7}, {%8,%9}, {%0,%1,%2,%3};"
        : "+f"(d[0]), "+f"(d[1]), "+f"(d[2]), "+f"(d[3])
        : "r"(a[0]), "r"(a[1]), "r"(a[2]), "r"(a[3]), "r"(b[0]), "r"(b[1]));
}

// ---------------- scratch (device globals) ----------------
__device__ __nv_bfloat16 g_fh[NFRM];                // frames hi
__device__ __nv_bfloat16 g_fl[NFRM];                // frames lo
__device__ __nv_bfloat16 g_b1p[C1 * K1P];           // W1' [576][2304] = [h|l|h]
__device__ __nv_bfloat16 g_w2p[DCNN * K2P];         // W2' [64][15552] per-tap [h|l|h]
__device__ __nv_bfloat16 g_f1bf[(size_t)BL * 81 * 1152]; // conv1 out, halo, ch=[hi576|lo576]
__device__ float g_y[M1 * DCNN];
__device__ float g_pool[BL * DCNN];
__device__ float g_s[BL * DRNN];
__device__ float g_gi[BL * G3];
__device__ float g_wiht[DRNN * G3];
__device__ float g_whht[DRNN * G3];
__device__ float g_fit[DRNN * DRNN];
__device__ float g_h[BATCH * DRNN];

// ---------------- prep: GRU weight transposes ----------------
__global__ void prep_kernel(const float* __restrict__ w_ih,
                            const float* __restrict__ w_hh,
                            const float* __restrict__ fi_w)
{
    int i = blockIdx.x * blockDim.x + threadIdx.x;
    if (i < DRNN * G3) {
        int g = i / DRNN, k = i % DRNN;
        g_wiht[k * G3 + g] = w_ih[i];
        g_whht[k * G3 + g] = w_hh[i];
    }
    if (i < DRNN * DRNN) {
        int d = i / DRNN, k = i % DRNN;
        g_fit[k * DRNN + d] = fi_w[i];
    }
}

// ---------------- bf16 hi/lo conversions ----------------
__device__ __forceinline__ void split_bf(float v, __nv_bfloat16& h, __nv_bfloat16& l) {
    h = __float2bfloat16_rn(v);
    l = __float2bfloat16_rn(v - __bfloat162float(h));
}

__global__ void cvt_frames_kernel(const float* __restrict__ f)
{
    int i = blockIdx.x * blockDim.x + threadIdx.x;
    if (i >= NFRM) return;
    __nv_bfloat16 h, l;
    split_bf(f[i], h, l);
    g_fh[i] = h;
    g_fl[i] = l;
}

__global__ void cvt_w1_kernel(const float* __restrict__ w1)
{
    int i = blockIdx.x * blockDim.x + threadIdx.x;
    if (i >= C1 * K1) return;
    int o = i / K1, k = i % K1;
    __nv_bfloat16 h, l;
    split_bf(w1[i], h, l);
    g_b1p[o * K1P + k] = h;
    g_b1p[o * K1P + 768 + k] = l;
    g_b1p[o * K1P + 1536 + k] = h;
}

__global__ void cvt_w2_kernel(const float* __restrict__ w2)
{
    int i = blockIdx.x * blockDim.x + threadIdx.x;
    if (i >= DCNN * 5184) return;
    int oc = i / 5184, r = i % 5184;
    int ic = r / 9, tap = r % 9;
    __nv_bfloat16 h, l;
    split_bf(w2[i], h, l);
    size_t base = (size_t)oc * K2P + tap * 1728;
    g_w2p[base + ic] = h;
    g_w2p[base + 576 + ic] = l;
    g_w2p[base + 1152 + ic] = h;
}

__global__ void halo_zero_kernel()
{
    int i = blockIdx.x * blockDim.x + threadIdx.x;   // 512*32*1152
    if (i >= BL * 32 * 1152) return;
    int ch = i % 1152;
    int t  = i / 1152;
    int c  = t % 32;
    int n  = t / 32;
    int yy, xx;
    if (c < 9)       { yy = 0;      xx = c; }
    else if (c < 18) { yy = 8;      xx = c - 9; }
    else if (c < 25) { yy = c - 17; xx = 0; }
    else             { yy = c - 24; xx = 8; }
    g_f1bf[((size_t)n * 81 + yy * 9 + xx) * 1152 + ch] = __float2bfloat16(0.f);
}

// =====================================================================
// mma.sync GEMM1: patchify conv (M=25088, N=576, K'=2304)
// CTA: 256 thr / 8 warps; tile 128x64; warp tile 32x32; chunk K=64
// =====================================================================
__global__ __launch_bounds__(256) void gemm1_tc(const float* __restrict__ b1)
{
    __shared__ __align__(128) char smA[2][16384];
    __shared__ __align__(128) char smB[2][8192];

    int tid = threadIdx.x, wid = tid >> 5, lid = tid & 31;
    int rowBase = blockIdx.x * 128;
    int cb = blockIdx.y * 64;
    int wm = (wid & 3) * 32;         // warp m offset
    int wn = (wid >> 2) * 32;        // warp n offset

    uint32_t aS[2] = { smem_u32(smA[0]), smem_u32(smA[1]) };
    uint32_t bS[2] = { smem_u32(smB[0]), smem_u32(smB[1]) };

    // per-thread cp.async units: 4 A (16B) + 2 B (16B)
    int aoff[4], adst[4];
#pragma unroll
    for (int e = 0; e < 4; e++) {
        int u = tid + e * 256;          // 0..1023
        int row = u >> 3, j = u & 7;
        int m = rowBase + row;
        int n = m / 49, p = m - n * 49;
        int py = p / 7, px = p - py * 7;
        aoff[e] = n * 37632 + (py * 16 + (j >> 1)) * 112 + px * 16 + (j & 1) * 8;
        adst[e] = SWZ(row * 128 + j * 16);
    }
    int boff[2], bdst[2];
#pragma unroll
    for (int e = 0; e < 2; e++) {
        int u = tid + e * 256;          // 0..511
        int r = u >> 3, j = u & 7;
        boff[e] = (cb + r) * K1P + j * 8;
        bdst[e] = SWZ(r * 128 + j * 16);
    }

    // ldmatrix base offsets
    int aLd[2], bLd[4];
#pragma unroll
    for (int mf = 0; mf < 2; mf++)
        aLd[mf] = (wm + mf * 16 + (lid & 15)) * 128 + ((lid >> 4) * 16);
#pragma unroll
    for (int nf = 0; nf < 4; nf++)
        bLd[nf] = (wn + nf * 8 + (lid & 7)) * 128 + (((lid >> 3) & 1) * 16);

    float acc[2][4][4];
#pragma unroll
    for (int mf = 0; mf < 2; mf++)
#pragma unroll
        for (int nf = 0; nf < 4; nf++)
#pragma unroll
            for (int q = 0; q < 4; q++) acc[mf][nf][q] = 0.f;

    // issue lambda
    auto issue = [&](int ch, int buf) {
        int term = ch / 12;
        const __nv_bfloat16* F = (term < 2) ? g_fh : g_fl;
        int k0 = (ch - term * 12) * 64;
        int c = k0 >> 8;
        int iy0 = (k0 & 255) >> 4;
        int add = c * 12544 + iy0 * 112;
#pragma unroll
        for (int e = 0; e < 4; e++)
            CP16(aS[buf] + adst[e], F + aoff[e] + add);
        int kb = ch * 64;
#pragma unroll
        for (int e = 0; e < 2; e++)
            CP16(bS[buf] + bdst[e], g_b1p + boff[e] + kb);
    };

    issue(0, 0); CP_COMMIT();
    for (int ch = 0; ch < NCH1; ch++) {
        int buf = ch & 1;
        if (ch + 1 < NCH1) { issue(ch + 1, buf ^ 1); CP_COMMIT(); CP_WAIT1(); }
        else CP_WAIT0();
        __syncthreads();

#pragma unroll
        for (int kk = 0; kk < 4; kk++) {
            uint32_t af[2][4], bf[4][2];
#pragma unroll
            for (int mf = 0; mf < 2; mf++)
                ldsm_x4(af[mf], aS[buf] + SWZ(aLd[mf] + kk * 32));
#pragma unroll
            for (int nf = 0; nf < 4; nf++)
                ldsm_x2(bf[nf], bS[buf] + SWZ(bLd[nf] + kk * 32));
#pragma unroll
            for (int mf = 0; mf < 2; mf++)
#pragma unroll
                for (int nf = 0; nf < 4; nf++)
                    mma16816(acc[mf][nf], af[mf], bf[nf]);
        }
        __syncthreads();
    }

    // epilogue: bias, split hi/lo, pack column pairs
#pragma unroll
    for (int mf = 0; mf < 2; mf++) {
#pragma unroll
        for (int half = 0; half < 2; half++) {
            int m = rowBase + wm + mf * 16 + half * 8 + (lid >> 2);
            int n = m / 49, p = m - n * 49;
            int py = p / 7, px = p - py * 7;
            size_t ob = ((size_t)n * 81 + (1 + py) * 9 + (1 + px)) * 1152;
#pragma unroll
            for (int nf = 0; nf < 4; nf++) {
                int c = cb + wn + nf * 8 + (lid & 3) * 2;
                float v0 = acc[mf][nf][half * 2 + 0] + b1[c];
                float v1 = acc[mf][nf][half * 2 + 1] + b1[c + 1];
                __nv_bfloat16 h0, l0, h1, l1;
                split_bf(v0, h0, l0);
                split_bf(v1, h1, l1);
                *(__nv_bfloat162*)(g_f1bf + ob + c) = __nv_bfloat162(h0, h1);
                *(__nv_bfloat162*)(g_f1bf + ob + 576 + c) = __nv_bfloat162(l0, l1);
            }
        }
    }
}

// =====================================================================
// mma.sync GEMM2: conv3x3 576->64 (M=25088, N=64, K'=15552)
// =====================================================================
__global__ __launch_bounds__(256) void gemm2_tc(const float* __restrict__ b2)
{
    __shared__ __align__(128) char smA[2][16384];
    __shared__ __align__(128) char smB[2][8192];

    int tid = threadIdx.x, wid = tid >> 5, lid = tid & 31;
    int rowBase = blockIdx.x * 128;
    int wm = (wid & 3) * 32;
    int wn = (wid >> 2) * 32;

    uint32_t aS[2] = { smem_u32(smA[0]), smem_u32(smA[1]) };
    uint32_t bS[2] = { smem_u32(smB[0]), smem_u32(smB[1]) };

    long apix[4]; int adst[4], aj8[4];
#pragma unroll
    for (int e = 0; e < 4; e++) {
        int u = tid + e * 256;
        int row = u >> 3, j = u & 7;
        int m = rowBase + row;
        int n = m / 49, p = m - n * 49;
        int py = p / 7, px = p - py * 7;
        apix[e] = (long)(n * 81 + (1 + py) * 9 + (1 + px)) * 1152;
        aj8[e] = j * 8;
        adst[e] = SWZ(row * 128 + j * 16);
    }
    int boff[2], bdst[2];
#pragma unroll
    for (int e = 0; e < 2; e++) {
        int u = tid + e * 256;
        int r = u >> 3, j = u & 7;
        boff[e] = r * K2P + j * 8;
        bdst[e] = SWZ(r * 128 + j * 16);
    }

    int aLd[2], bLd[4];
#pragma unroll
    for (int mf = 0; mf < 2; mf++)
        aLd[mf] = (wm + mf * 16 + (lid & 15)) * 128 + ((lid >> 4) * 16);
#pragma unroll
    for (int nf = 0; nf < 4; nf++)
        bLd[nf] = (wn + nf * 8 + (lid & 7)) * 128 + (((lid >> 3) & 1) * 16);

    float acc[2][4][4];
#pragma unroll
    for (int mf = 0; mf < 2; mf++)
#pragma unroll
        for (int nf = 0; nf < 4; nf++)
#pragma unroll
            for (int q = 0; q < 4; q++) acc[mf][nf][q] = 0.f;

    auto issue = [&](int ch, int buf) {
        int tap = ch / 27;
        int r0 = (ch - tap * 27) * 64;
        int choff = (r0 < 576) ? r0 : (r0 - 576);   // [h|l|h] plane mapping
        int pixd = ((tap / 3) - 1) * 9 + (tap % 3) - 1;
        long add = (long)pixd * 1152 + choff;
#pragma unroll
        for (int e = 0; e < 4; e++)
            CP16(aS[buf] + adst[e], g_f1bf + (apix[e] + add + aj8[e]));
        int kb = ch * 64;
#pragma unroll
        for (int e = 0; e < 2; e++)
            CP16(bS[buf] + bdst[e], g_w2p + boff[e] + kb);
    };

    issue(0, 0); CP_COMMIT();
    for (int ch = 0; ch < NCH2; ch++) {
        int buf = ch & 1;
        if (ch + 1 < NCH2) { issue(ch + 1, buf ^ 1); CP_COMMIT(); CP_WAIT1(); }
        else CP_WAIT0();
        __syncthreads();

#pragma unroll
        for (int kk = 0; kk < 4; kk++) {
            uint32_t af[2][4], bf[4][2];
#pragma unroll
            for (int mf = 0; mf < 2; mf++)
                ldsm_x4(af[mf], aS[buf] + SWZ(aLd[mf] + kk * 32));
#pragma unroll
            for (int nf = 0; nf < 4; nf++)
                ldsm_x2(bf[nf], bS[buf] + SWZ(bLd[nf] + kk * 32));
#pragma unroll
            for (int mf = 0; mf < 2; mf++)
#pragma unroll
                for (int nf = 0; nf < 4; nf++)
                    mma16816(acc[mf][nf], af[mf], bf[nf]);
        }
        __syncthreads();
    }

#pragma unroll
    for (int mf = 0; mf < 2; mf++) {
#pragma unroll
        for (int half = 0; half < 2; half++) {
            int m = rowBase + wm + mf * 16 + half * 8 + (lid >> 2);
#pragma unroll
            for (int nf = 0; nf < 4; nf++) {
                int c = wn + nf * 8 + (lid & 3) * 2;
                float2 v;
                v.x = acc[mf][nf][half * 2 + 0] + b2[c];
                v.y = acc[mf][nf][half * 2 + 1] + b2[c + 1];
                *(float2*)(g_y + (size_t)m * DCNN + c) = v;
            }
        }
    }
}

// ---------------- relu + BN + mean-pool ----------------
__global__ void pool_kernel(const float* __restrict__ bn_g,
                            const float* __restrict__ bn_b,
                            const float* __restrict__ bn_m,
                            const float* __restrict__ bn_v)
{
    int n  = blockIdx.x;
    int oc = threadIdx.x;
    float s = 0.f;
    const float* bp = g_y + (size_t)n * 49 * DCNN + oc;
#pragma unroll
    for (int p = 0; p < 49; p++) s += fmaxf(bp[p * DCNN], 0.f);
    float inv = bn_g[oc] * rsqrtf(bn_v[oc] + 1e-5f);
    g_pool[n * DCNN + oc] = (s * (1.f / 49.f) - bn_m[oc]) * inv + bn_b[oc];
}

// ---------------- state adapters + concat + an ----------------
__global__ void adapter_kernel(const float* __restrict__ x,
                               const float* __restrict__ a0_w, const float* __restrict__ a0_b,
                               const float* __restrict__ ai_w, const float* __restrict__ ai_b,
                               const float* __restrict__ an_w, const float* __restrict__ an_b)
{
    int r = blockIdx.x;
    int tid = threadIdx.x;
    __shared__ float s0[16];
    __shared__ float cat[80];

    const float* xr = x + r * 12;
    if (tid < 16) {
        float a = a0_b[tid];
#pragma unroll
        for (int j = 0; j < 12; j++) a += xr[j] * a0_w[tid * 12 + j];
        s0[tid] = fmaxf(a, 0.f);
    }
    __syncthreads();
    if (tid < 16) {
        float a = ai_b[tid];
#pragma unroll
        for (int j = 0; j < 16; j++) a += s0[j] * ai_w[tid * 16 + j];
        cat[tid] = s0[tid] + fmaxf(a, 0.f);
    }
    if (tid >= 32 && tid < 96) cat[16 + tid - 32] = g_pool[r * DCNN + tid - 32];
    __syncthreads();

    float a = an_b[tid];
#pragma unroll
    for (int j = 0; j < 80; j++) a += cat[j] * an_w[tid * 80 + j];
    g_s[r * DRNN + tid] = fmaxf(a, 0.f);
}

// ---------------- encoder input gates ----------------
__global__ __launch_bounds__(256) void gi_kernel(const float* __restrict__ b_ih)
{
    int blk = blockIdx.x;
    int d = threadIdx.x;
    __shared__ __align__(16) float svT[DRNN][16];

    for (int rr = 0; rr < 16; rr++) {
        int q = blk * 16 + rr;
        int t = q >> 5, b = q & 31;
        int r = b * 16 + t;
        svT[d][rr] = g_s[r * DRNN + d];
    }
    __syncthreads();

    float a0[16], a1[16], a2[16];
#pragma unroll
    for (int rr = 0; rr < 16; rr++) { a0[rr] = 0.f; a1[rr] = 0.f; a2[rr] = 0.f; }

    for (int k = 0; k < DRNN; k++) {
        const float* w = g_wiht + k * G3 + d;
        float w0 = w[0], w1 = w[256], w2 = w[512];
        const float4* s4 = (const float4*)&svT[k][0];
#pragma unroll
        for (int c = 0; c < 4; c++) {
            float4 sv = s4[c];
            float s[4] = {sv.x, sv.y, sv.z, sv.w};
#pragma unroll
            for (int u = 0; u < 4; u++) {
                int rr = c * 4 + u;
                a0[rr] += s[u] * w0;
                a1[rr] += s[u] * w1;
                a2[rr] += s[u] * w2;
            }
        }
    }

    float bi0 = b_ih[d], bi1 = b_ih[256 + d], bi2 = b_ih[512 + d];
#pragma unroll
    for (int rr = 0; rr < 16; rr++) {
        float* o = g_gi + (size_t)(blk * 16 + rr) * G3;
        o[d] = a0[rr] + bi0;
        o[256 + d] = a1[rr] + bi1;
        o[512 + d] = a2[rr] + bi2;
    }
}

__device__ __forceinline__ float sigmoidf_(float v) { return 1.f / (1.f + expf(-v)); }

// ---------------- fused encoder ----------------
__global__ __launch_bounds__(256) void encoder_kernel(const float* __restrict__ b_hh)
{
    int b = blockIdx.x;
    int d = threadIdx.x;
    __shared__ float hs[DRNN];
    hs[d] = 0.f;
    __syncthreads();

    float bh0 = b_hh[d], bh1 = b_hh[256 + d], bh2 = b_hh[512 + d];

    for (int t = 0; t < LSEQ; t++) {
        float a0 = bh0, a1 = bh1, a2 = bh2;
#pragma unroll 4
        for (int k = 0; k < DRNN; k++) {
            float h = hs[k];
            const float* w = g_whht + k * G3 + d;
            a0 += h * w[0];
            a1 += h * w[256];
            a2 += h * w[512];
        }
        const float* gi = g_gi + (size_t)(t * 32 + b) * G3;
        float rr = sigmoidf_(gi[d] + a0);
        float zz = sigmoidf_(gi[256 + d] + a1);
        float nn = tanhf(gi[512 + d] + rr * a2);
        float newh = (1.f - zz) * nn + zz * hs[d];
        __syncthreads();
        hs[d] = newh;
        __syncthreads();
    }
    g_h[b * DRNN + d] = hs[d];
}

// ---------------- fused decoder ----------------
__global__ __launch_bounds__(256) void decoder_kernel(
    const float* __restrict__ b_ih, const float* __restrict__ b_hh,
    const float* __restrict__ fi_b,
    const float* __restrict__ fn_w, const float* __restrict__ fn_b,
    float* __restrict__ out)
{
    int b = blockIdx.x;
    int d = threadIdx.x;
    __shared__ float hs[DRNN];
    __shared__ float xs[DRNN];
    __shared__ float xr[DRNN];

    float h0 = g_h[b * DRNN + d];
    hs[d] = h0;
    xs[d] = h0;
    __syncthreads();

    float bh0 = b_hh[d], bh1 = b_hh[256 + d], bh2 = b_hh[512 + d];
    float bi0 = b_ih[d], bi1 = b_ih[256 + d], bi2 = b_ih[512 + d];
    float fib = fi_b[d];

    for (int t = 0; t < HORIZON; t++) {
        float a0 = bh0, a1 = bh1, a2 = bh2;
        float c0 = bi0, c1 = bi1, c2 = bi2;
#pragma unroll 4
        for (int k = 0; k < DRNN; k++) {
            float h = hs[k];
            float xv = xs[k];
            const float* wh = g_whht + k * G3 + d;
            const float* wi = g_wiht + k * G3 + d;
            a0 += h * wh[0];  a1 += h * wh[256];  a2 += h * wh[512];
            c0 += xv * wi[0]; c1 += xv * wi[256]; c2 += xv * wi[512];
        }
        float rr = sigmoidf_(c0 + a0);
        float zz = sigmoidf_(c1 + a1);
        float nn = tanhf(c2 + rr * a2);
        float newh = (1.f - zz) * nn + zz * hs[d];
        __syncthreads();
        hs[d] = newh;
        __syncthreads();

        float a = fib;
#pragma unroll 4
        for (int k = 0; k < DRNN; k++) a += hs[k] * g_fit[k * DRNN + d];
        float v = hs[d] + fmaxf(a, 0.f);
        xr[d] = v;
        xs[d] = v;
        __syncthreads();

        if (d < 2) {
            float s = fn_b[d];
            for (int k = 0; k < DRNN; k++) s += xr[k] * fn_w[d * DRNN + k];
            out[(t * 32 + b) * 2 + d] = tanhf(s);
        }
        __syncthreads();
    }
}

// ---------------- launch ----------------
extern "C" void kernel_launch(void* const* d_in, const int* in_sizes, int n_in,
                              void* d_out, int out_size)
{
    const float* x      = (const float*)d_in[0];
    const float* frames = (const float*)d_in[1];
    const float* cnn_w  = (const float*)d_in[2];
    const float* cnn_b  = (const float*)d_in[3];
    const float* cnn1_w = (const float*)d_in[4];
    const float* cnn1_b = (const float*)d_in[5];
    const float* bn_g   = (const float*)d_in[6];
    const float* bn_b   = (const float*)d_in[7];
    const float* bn_m   = (const float*)d_in[8];
    const float* bn_v   = (const float*)d_in[9];
    const float* a0_w   = (const float*)d_in[10];
    const float* a0_b   = (const float*)d_in[11];
    const float* ai_w   = (const float*)d_in[12];
    const float* ai_b   = (const float*)d_in[13];
    const float* an_w   = (const float*)d_in[14];
    const float* an_b   = (const float*)d_in[15];
    const float* w_ih   = (const float*)d_in[16];
    const float* w_hh   = (const float*)d_in[17];
    const float* b_ih   = (const float*)d_in[18];
    const float* b_hh   = (const float*)d_in[19];
    const float* fi_w   = (const float*)d_in[20];
    const float* fi_b   = (const float*)d_in[21];
    const float* fn_w   = (const float*)d_in[22];
    const float* fn_b   = (const float*)d_in[23];
    float* out = (float*)d_out;

    prep_kernel<<<(DRNN * G3 + 255) / 256, 256>>>(w_ih, w_hh, fi_w);
    cvt_frames_kernel<<<(NFRM + 255) / 256, 256>>>(frames);
    cvt_w1_kernel<<<(C1 * K1 + 255) / 256, 256>>>(cnn_w);
    cvt_w2_kernel<<<(DCNN * 5184 + 255) / 256, 256>>>(cnn1_w);
    halo_zero_kernel<<<(BL * 32 * 1152 + 255) / 256, 256>>>();

    dim3 g1(M1 / 128, C1 / 64);
    gemm1_tc<<<g1, 256>>>(cnn_b);
    gemm2_tc<<<M1 / 128, 256>>>(cnn1_b);

    pool_kernel<<<BL, DCNN>>>(bn_g, bn_b, bn_m, bn_v);
    adapter_kernel<<<BL, DRNN>>>(x, a0_w, a0_b, ai_w, ai_b, an_w, an_b);
    gi_kernel<<<BL / 16, DRNN>>>(b_ih);

    encoder_kernel<<<BATCH, DRNN>>>(b_hh);
    decoder_kernel<<<BATCH, DRNN>>>(b_ih, b_hh, fi_b, fn_w, fn_b, out);
}

// round 5
// speedup vs baseline: 1.4265x; 1.4265x over previous
#include <cuda_runtime.h>
#include <math.h>
#include <cstdint>

// ---------------- problem constants ----------------
#define BATCH   32
#define LSEQ    16
#define BL      512
#define M1      25088        // BL * 49
#define C1      576
#define DCNN    64
#define DRNN    256
#define G3      768
#define HORIZON 10

#define KC      6912         // fused conv K = 3*48*48
#define KSPLIT  4
#define KPER    1728         // KC / KSPLIT
#define NCH     108          // KPER / 16
#define FPAD    62208        // 3*144*144
#define FPLANE  20736        // 144*144

typedef unsigned long long u64;

__device__ __forceinline__ void ffma2(u64 &c, u64 a, u64 b) {
    asm("fma.rn.f32x2 %0, %1, %2, %0;" : "+l"(c) : "l"(a), "l"(b));
}
__device__ __forceinline__ u64 dup2(float v) {
    u64 r; asm("mov.b64 %0, {%1,%2};" : "=l"(r) : "f"(v), "f"(v)); return r;
}
__device__ __forceinline__ float2 unpack2(u64 v) {
    float2 f; asm("mov.b64 {%0,%1}, %2;" : "=f"(f.x), "=f"(f.y) : "l"(v)); return f;
}

// ---------------- scratch (device globals) ----------------
__device__ float g_fpad[(size_t)BL * FPAD];      // padded frames (512,3,144,144) ~127MB
__device__ float g_wcT[KC * DCNN];               // fused conv weight, [k][oc]
__device__ float g_t[DCNN * 9];                  // per-tap bias contribution
__device__ float g_bb[49 * DCNN];                // bias field [p][oc]
__device__ float g_yp[KSPLIT * M1 * DCNN];       // GEMM partials
__device__ float g_pool[BL * DCNN];
__device__ float g_s[BL * DRNN];
__device__ float g_gi[BL * G3];
__device__ float g_wiht[DRNN * G3];
__device__ float g_whht[DRNN * G3];
__device__ float g_fit[DRNN * DRNN];
__device__ float g_h[BATCH * DRNN];

// ---------------- prep: GRU weight transposes ----------------
__global__ void prep_kernel(const float* __restrict__ w_ih,
                            const float* __restrict__ w_hh,
                            const float* __restrict__ fi_w)
{
    int i = blockIdx.x * blockDim.x + threadIdx.x;
    if (i < DRNN * G3) {
        int g = i / DRNN, k = i % DRNN;
        g_wiht[k * G3 + g] = w_ih[i];
        g_whht[k * G3 + g] = w_hh[i];
    }
    if (i < DRNN * DRNN) {
        int d = i / DRNN, k = i % DRNN;
        g_fit[k * DRNN + d] = fi_w[i];
    }
}

// ---------------- padded frames copy ----------------
__global__ void pad_frames_kernel(const float* __restrict__ frames)
{
    int i = blockIdx.x * blockDim.x + threadIdx.x;
    if (i >= BL * FPAD) return;
    int n = i / FPAD, r = i - n * FPAD;
    int c = r / FPLANE, rr = r - c * FPLANE;
    int y = rr / 144, x = rr - y * 144;
    float v = 0.f;
    if (y >= 16 && y < 128 && x >= 16 && x < 128)
        v = frames[n * 37632 + c * 12544 + (y - 16) * 112 + (x - 16)];
    g_fpad[(size_t)i] = v;
}

// ---------------- fused conv weight: Wc = W2 o W1 ----------------
// grid (12 j-tiles, 9 taps), 256 threads; tile [64 oc][64 j], K=576 (mc)
__global__ __launch_bounds__(256) void wc_gemm(const float* __restrict__ cnn1_w,
                                               const float* __restrict__ cnn_w)
{
    __shared__ float As[16][68];   // [mc][oc]
    __shared__ float Bs[16][68];   // [mc][j]
    int tid = threadIdx.x;
    int jt = blockIdx.x, tap = blockIdx.y;
    int ty16 = tap / 3, tx16 = tap - ty16 * 3;
    int tx = tid & 15, ty = tid >> 4;

    float acc[4][4];
#pragma unroll
    for (int i = 0; i < 4; i++)
#pragma unroll
        for (int j = 0; j < 4; j++) acc[i][j] = 0.f;

    int kkB = tid >> 4, j4 = (tid & 15) * 4;
    for (int mc0 = 0; mc0 < C1; mc0 += 16) {
#pragma unroll
        for (int e = 0; e < 4; e++) {
            int u = tid + e * 256;
            int oc = u >> 4, kk = u & 15;
            As[kk][oc] = cnn1_w[oc * 5184 + (mc0 + kk) * 9 + tap];
        }
        *(float4*)&Bs[kkB][j4] = *(const float4*)(cnn_w + (mc0 + kkB) * 768 + jt * 64 + j4);
        __syncthreads();
#pragma unroll
        for (int kk = 0; kk < 16; kk++) {
            float a[4], b[4];
#pragma unroll
            for (int i = 0; i < 4; i++) a[i] = As[kk][ty * 4 + i];
#pragma unroll
            for (int j = 0; j < 4; j++) b[j] = Bs[kk][tx * 4 + j];
#pragma unroll
            for (int i = 0; i < 4; i++)
#pragma unroll
                for (int j = 0; j < 4; j++) acc[i][j] += a[i] * b[j];
        }
        __syncthreads();
    }

#pragma unroll
    for (int i = 0; i < 4; i++) {
        int oc = ty * 4 + i;
#pragma unroll
        for (int jj = 0; jj < 4; jj++) {
            int j = jt * 64 + tx * 4 + jj;
            int c = j >> 8, rem = j & 255;
            int iy = rem >> 4, ix = rem & 15;
            int k = c * 2304 + (ty16 * 16 + iy) * 48 + tx16 * 16 + ix;
            g_wcT[k * DCNN + oc] = acc[i][jj];
        }
    }
}

// ---------------- per-tap bias t[oc][tap] = sum_mc W2*b1 ----------------
__global__ void bias_t_kernel(const float* __restrict__ cnn1_w,
                              const float* __restrict__ b1)
{
    __shared__ float b1s[C1];
    int tid = threadIdx.x;
    if (tid < C1) b1s[tid] = b1[tid];
    __syncthreads();
    if (tid >= DCNN * 9) return;
    int oc = tid / 9, tap = tid - oc * 9;
    float s = 0.f;
    for (int mc = 0; mc < C1; mc++)
        s += cnn1_w[oc * 5184 + mc * 9 + tap] * b1s[mc];
    g_t[oc * 9 + tap] = s;
}

// ---------------- bias field bb[p][oc] ----------------
__global__ void bias_bb_kernel(const float* __restrict__ b2)
{
    int p = blockIdx.x;          // 0..48
    int oc = threadIdx.x;        // 0..63
    int py = p / 7, px = p - py * 7;
    float s = b2[oc];
#pragma unroll
    for (int ty = 0; ty < 3; ty++)
#pragma unroll
        for (int tx = 0; tx < 3; tx++) {
            int ny = py + ty - 1, nx = px + tx - 1;
            if ((unsigned)ny < 7u && (unsigned)nx < 7u)
                s += g_t[oc * 9 + ty * 3 + tx];
        }
    g_bb[p * DCNN + oc] = s;
}

// =====================================================================
// fused conv GEMM: M=25088, N=64, K=6912, split 4-way over K
// CTA 256 thr, tile 128x64, thread tile 8x4, KT=16, register-staged
// =====================================================================
__global__ __launch_bounds__(256) void fused_gemm(void)
{
    __shared__ __align__(16) float As[16][132];
    __shared__ __align__(16) float Bs[16][68];

    int tid = threadIdx.x;
    int tx = tid & 15, ty = tid >> 4;
    int rowBase = blockIdx.x * 128;
    int ks = blockIdx.y;
    int kbase = ks * KPER;

    // A staging units: 2 per thread (each float4)
    int abase[2], arow[2], aq4[2];
#pragma unroll
    for (int e = 0; e < 2; e++) {
        int idx = tid + e * 256;           // 0..511
        int row = idx >> 2, q4 = idx & 3;
        int m = rowBase + row;
        int n = m / 49, p = m - n * 49;
        int py = p / 7, px = p - py * 7;
        abase[e] = n * FPAD + (py * 16) * 144 + px * 16;
        arow[e] = row;
        aq4[e] = q4;
    }
    int kkB = tid >> 4, j4 = (tid & 15) * 4;

    u64 acc2[4][4];
#pragma unroll
    for (int i = 0; i < 4; i++)
#pragma unroll
        for (int j = 0; j < 4; j++) acc2[i][j] = 0ull;

    // chunk offset helper
    auto chunk_off = [&](int ch) {
        int k0 = kbase + ch * 16;
        int c = k0 / 2304;
        int r = k0 - c * 2304;
        int wy = r / 48;
        int wx0 = r - wy * 48;
        return c * FPLANE + wy * 144 + wx0;
    };

    // prologue: stage chunk 0
    float4 ra[2], rb;
    {
        int off = chunk_off(0);
#pragma unroll
        for (int e = 0; e < 2; e++)
            ra[e] = *(const float4*)(g_fpad + (size_t)abase[e] + off + aq4[e] * 4);
        rb = *(const float4*)(g_wcT + (size_t)(kbase + kkB) * DCNN + j4);
    }

    for (int ch = 0; ch < NCH; ch++) {
        // commit staged regs to smem
#pragma unroll
        for (int e = 0; e < 2; e++) {
            int b0 = aq4[e] * 4, r = arow[e];
            As[b0 + 0][r] = ra[e].x;
            As[b0 + 1][r] = ra[e].y;
            As[b0 + 2][r] = ra[e].z;
            As[b0 + 3][r] = ra[e].w;
        }
        *(float4*)&Bs[kkB][j4] = rb;
        __syncthreads();

        // stage next chunk (overlaps compute)
        if (ch + 1 < NCH) {
            int off = chunk_off(ch + 1);
#pragma unroll
            for (int e = 0; e < 2; e++)
                ra[e] = *(const float4*)(g_fpad + (size_t)abase[e] + off + aq4[e] * 4);
            rb = *(const float4*)(g_wcT + (size_t)(kbase + (ch + 1) * 16 + kkB) * DCNN + j4);
        }

#pragma unroll
        for (int kk = 0; kk < 16; kk++) {
            ulonglong2 A0 = *(const ulonglong2*)&As[kk][ty * 8];
            ulonglong2 A1 = *(const ulonglong2*)&As[kk][ty * 8 + 4];
            float4 b4 = *(const float4*)&Bs[kk][tx * 4];
            u64 ap[4] = {A0.x, A0.y, A1.x, A1.y};
            u64 bd[4] = {dup2(b4.x), dup2(b4.y), dup2(b4.z), dup2(b4.w)};
#pragma unroll
            for (int i = 0; i < 4; i++)
#pragma unroll
                for (int j = 0; j < 4; j++) ffma2(acc2[i][j], ap[i], bd[j]);
        }
        __syncthreads();
    }

    // epilogue: write partials (no bias; bias via g_bb in pool)
    float* outp = g_yp + (size_t)ks * M1 * DCNN;
#pragma unroll
    for (int i2 = 0; i2 < 4; i2++) {
        int m0 = rowBase + ty * 8 + 2 * i2;
        float2 u0 = unpack2(acc2[i2][0]);
        float2 u1 = unpack2(acc2[i2][1]);
        float2 u2 = unpack2(acc2[i2][2]);
        float2 u3 = unpack2(acc2[i2][3]);
        float4 e0 = {u0.x, u1.x, u2.x, u3.x};
        float4 e1 = {u0.y, u1.y, u2.y, u3.y};
        *(float4*)(outp + (size_t)m0 * DCNN + tx * 4) = e0;
        *(float4*)(outp + (size_t)(m0 + 1) * DCNN + tx * 4) = e1;
    }
}

// ---------------- pool: sum partials + bias field + relu + BN + mean ---
__global__ void pool_kernel(const float* __restrict__ bn_g,
                            const float* __restrict__ bn_b,
                            const float* __restrict__ bn_m,
                            const float* __restrict__ bn_v)
{
    int n  = blockIdx.x;
    int oc = threadIdx.x;
    const float* p0 = g_yp + (size_t)n * 49 * DCNN + oc;
    const float* p1 = p0 + (size_t)M1 * DCNN;
    const float* p2 = p1 + (size_t)M1 * DCNN;
    const float* p3 = p2 + (size_t)M1 * DCNN;
    float s = 0.f;
#pragma unroll
    for (int p = 0; p < 49; p++) {
        float v = p0[p * DCNN] + p1[p * DCNN] + p2[p * DCNN] + p3[p * DCNN]
                + g_bb[p * DCNN + oc];
        s += fmaxf(v, 0.f);
    }
    float inv = bn_g[oc] * rsqrtf(bn_v[oc] + 1e-5f);
    g_pool[n * DCNN + oc] = (s * (1.f / 49.f) - bn_m[oc]) * inv + bn_b[oc];
}

// ---------------- state adapters + concat + an ----------------
__global__ void adapter_kernel(const float* __restrict__ x,
                               const float* __restrict__ a0_w, const float* __restrict__ a0_b,
                               const float* __restrict__ ai_w, const float* __restrict__ ai_b,
                               const float* __restrict__ an_w, const float* __restrict__ an_b)
{
    int r = blockIdx.x;
    int tid = threadIdx.x;
    __shared__ float s0[16];
    __shared__ float cat[80];

    const float* xr = x + r * 12;
    if (tid < 16) {
        float a = a0_b[tid];
#pragma unroll
        for (int j = 0; j < 12; j++) a += xr[j] * a0_w[tid * 12 + j];
        s0[tid] = fmaxf(a, 0.f);
    }
    __syncthreads();
    if (tid < 16) {
        float a = ai_b[tid];
#pragma unroll
        for (int j = 0; j < 16; j++) a += s0[j] * ai_w[tid * 16 + j];
        cat[tid] = s0[tid] + fmaxf(a, 0.f);
    }
    if (tid >= 32 && tid < 96) cat[16 + tid - 32] = g_pool[r * DCNN + tid - 32];
    __syncthreads();

    float a = an_b[tid];
#pragma unroll
    for (int j = 0; j < 80; j++) a += cat[j] * an_w[tid * 80 + j];
    g_s[r * DRNN + tid] = fmaxf(a, 0.f);
}

// ---------------- encoder input gates (tiled GEMM) ----------------
__global__ __launch_bounds__(256) void gi_kernel(const float* __restrict__ b_ih)
{
    int blk = blockIdx.x;
    int d = threadIdx.x;
    __shared__ __align__(16) float svT[DRNN][16];

    for (int rr = 0; rr < 16; rr++) {
        int q = blk * 16 + rr;
        int t = q >> 5, b = q & 31;
        int r = b * 16 + t;
        svT[d][rr] = g_s[r * DRNN + d];
    }
    __syncthreads();

    float a0[16], a1[16], a2[16];
#pragma unroll
    for (int rr = 0; rr < 16; rr++) { a0[rr] = 0.f; a1[rr] = 0.f; a2[rr] = 0.f; }

    for (int k = 0; k < DRNN; k++) {
        const float* w = g_wiht + k * G3 + d;
        float w0 = w[0], w1 = w[256], w2 = w[512];
        const float4* s4 = (const float4*)&svT[k][0];
#pragma unroll
        for (int c = 0; c < 4; c++) {
            float4 sv = s4[c];
            float s[4] = {sv.x, sv.y, sv.z, sv.w};
#pragma unroll
            for (int u = 0; u < 4; u++) {
                int rr = c * 4 + u;
                a0[rr] += s[u] * w0;
                a1[rr] += s[u] * w1;
                a2[rr] += s[u] * w2;
            }
        }
    }

    float bi0 = b_ih[d], bi1 = b_ih[256 + d], bi2 = b_ih[512 + d];
#pragma unroll
    for (int rr = 0; rr < 16; rr++) {
        float* o = g_gi + (size_t)(blk * 16 + rr) * G3;
        o[d] = a0[rr] + bi0;
        o[256 + d] = a1[rr] + bi1;
        o[512 + d] = a2[rr] + bi2;
    }
}

__device__ __forceinline__ float sigmoidf_(float v) { return 1.f / (1.f + expf(-v)); }

// ---------------- fused encoder ----------------
__global__ __launch_bounds__(256) void encoder_kernel(const float* __restrict__ b_hh)
{
    int b = blockIdx.x;
    int d = threadIdx.x;
    __shared__ float hs[DRNN];
    hs[d] = 0.f;
    __syncthreads();

    float bh0 = b_hh[d], bh1 = b_hh[256 + d], bh2 = b_hh[512 + d];

    for (int t = 0; t < LSEQ; t++) {
        float a0 = bh0, a1 = bh1, a2 = bh2;
#pragma unroll 4
        for (int k = 0; k < DRNN; k++) {
            float h = hs[k];
            const float* w = g_whht + k * G3 + d;
            a0 += h * w[0];
            a1 += h * w[256];
            a2 += h * w[512];
        }
        const float* gi = g_gi + (size_t)(t * 32 + b) * G3;
        float rr = sigmoidf_(gi[d] + a0);
        float zz = sigmoidf_(gi[256 + d] + a1);
        float nn = tanhf(gi[512 + d] + rr * a2);
        float newh = (1.f - zz) * nn + zz * hs[d];
        __syncthreads();
        hs[d] = newh;
        __syncthreads();
    }
    g_h[b * DRNN + d] = hs[d];
}

// ---------------- fused decoder ----------------
__global__ __launch_bounds__(256) void decoder_kernel(
    const float* __restrict__ b_ih, const float* __restrict__ b_hh,
    const float* __restrict__ fi_b,
    const float* __restrict__ fn_w, const float* __restrict__ fn_b,
    float* __restrict__ out)
{
    int b = blockIdx.x;
    int d = threadIdx.x;
    __shared__ float hs[DRNN];
    __shared__ float xs[DRNN];
    __shared__ float xr[DRNN];

    float h0 = g_h[b * DRNN + d];
    hs[d] = h0;
    xs[d] = h0;
    __syncthreads();

    float bh0 = b_hh[d], bh1 = b_hh[256 + d], bh2 = b_hh[512 + d];
    float bi0 = b_ih[d], bi1 = b_ih[256 + d], bi2 = b_ih[512 + d];
    float fib = fi_b[d];

    for (int t = 0; t < HORIZON; t++) {
        float a0 = bh0, a1 = bh1, a2 = bh2;
        float c0 = bi0, c1 = bi1, c2 = bi2;
#pragma unroll 4
        for (int k = 0; k < DRNN; k++) {
            float h = hs[k];
            float xv = xs[k];
            const float* wh = g_whht + k * G3 + d;
            const float* wi = g_wiht + k * G3 + d;
            a0 += h * wh[0];  a1 += h * wh[256];  a2 += h * wh[512];
            c0 += xv * wi[0]; c1 += xv * wi[256]; c2 += xv * wi[512];
        }
        float rr = sigmoidf_(c0 + a0);
        float zz = sigmoidf_(c1 + a1);
        float nn = tanhf(c2 + rr * a2);
        float newh = (1.f - zz) * nn + zz * hs[d];
        __syncthreads();
        hs[d] = newh;
        __syncthreads();

        float a = fib;
#pragma unroll 4
        for (int k = 0; k < DRNN; k++) a += hs[k] * g_fit[k * DRNN + d];
        float v = hs[d] + fmaxf(a, 0.f);
        xr[d] = v;
        xs[d] = v;
        __syncthreads();

        if (d < 2) {
            float s = fn_b[d];
            for (int k = 0; k < DRNN; k++) s += xr[k] * fn_w[d * DRNN + k];
            out[(t * 32 + b) * 2 + d] = tanhf(s);
        }
        __syncthreads();
    }
}

// ---------------- launch ----------------
extern "C" void kernel_launch(void* const* d_in, const int* in_sizes, int n_in,
                              void* d_out, int out_size)
{
    const float* x      = (const float*)d_in[0];
    const float* frames = (const float*)d_in[1];
    const float* cnn_w  = (const float*)d_in[2];
    const float* cnn_b  = (const float*)d_in[3];
    const float* cnn1_w = (const float*)d_in[4];
    const float* cnn1_b = (const float*)d_in[5];
    const float* bn_g   = (const float*)d_in[6];
    const float* bn_b   = (const float*)d_in[7];
    const float* bn_m   = (const float*)d_in[8];
    const float* bn_v   = (const float*)d_in[9];
    const float* a0_w   = (const float*)d_in[10];
    const float* a0_b   = (const float*)d_in[11];
    const float* ai_w   = (const float*)d_in[12];
    const float* ai_b   = (const float*)d_in[13];
    const float* an_w   = (const float*)d_in[14];
    const float* an_b   = (const float*)d_in[15];
    const float* w_ih   = (const float*)d_in[16];
    const float* w_hh   = (const float*)d_in[17];
    const float* b_ih   = (const float*)d_in[18];
    const float* b_hh   = (const float*)d_in[19];
    const float* fi_w   = (const float*)d_in[20];
    const float* fi_b   = (const float*)d_in[21];
    const float* fn_w   = (const float*)d_in[22];
    const float* fn_b   = (const float*)d_in[23];
    float* out = (float*)d_out;

    prep_kernel<<<(DRNN * G3 + 255) / 256, 256>>>(w_ih, w_hh, fi_w);
    pad_frames_kernel<<<(BL * FPAD + 255) / 256, 256>>>(frames);

    dim3 gw(12, 9);
    wc_gemm<<<gw, 256>>>(cnn1_w, cnn_w);
    bias_t_kernel<<<1, 576>>>(cnn1_w, cnn_b);
    bias_bb_kernel<<<49, DCNN>>>(cnn1_b);

    dim3 gg(M1 / 128, KSPLIT);
    fused_gemm<<<gg, 256>>>();

    pool_kernel<<<BL, DCNN>>>(bn_g, bn_b, bn_m, bn_v);
    adapter_kernel<<<BL, DRNN>>>(x, a0_w, a0_b, ai_w, ai_b, an_w, an_b);
    gi_kernel<<<BL / 16, DRNN>>>(b_ih);

    encoder_kernel<<<BATCH, DRNN>>>(b_hh);
    decoder_kernel<<<BATCH, DRNN>>>(b_ih, b_hh, fi_b, fn_w, fn_b, out);
}

// round 8
// speedup vs baseline: 2.1988x; 1.5414x over previous
#include <cuda_runtime.h>
#include <math.h>
#include <cstdint>

// ---------------- problem constants ----------------
#define BATCH   32
#define LSEQ    16
#define BL      512
#define M1      25088        // BL * 49
#define C1      576
#define DCNN    64
#define DRNN    256
#define G3      768
#define HORIZON 10

#define KC      6912         // fused conv K = 3*48*48
#define KSPLIT  6
#define KPER    1152         // KC / KSPLIT
#define NCH     72           // KPER / 16
#define FPAD    62208        // 3*144*144
#define FPLANE  20736        // 144*144

// ---------------- scratch (device globals) ----------------
__device__ float g_fpad[(size_t)BL * FPAD];      // padded frames (512,3,144,144)
__device__ float g_wcT[KC * DCNN];               // fused conv weight, [k][oc]
__device__ float g_t[DCNN * 9];                  // per-tap bias contribution
__device__ float g_bb[49 * DCNN];                // bias field [p][oc]
__device__ float g_yp[(size_t)KSPLIT * M1 * DCNN]; // GEMM partials
__device__ float g_pool[BL * DCNN];
__device__ float g_s[BL * DRNN];
__device__ float g_gi[BL * G3];
// packed GRU weights: [kq][gate][d][4]  (kq = k/4)
__device__ float g_wihp[G3 * DRNN];
__device__ float g_whhp[G3 * DRNN];
__device__ float g_fitp[DRNN * DRNN];            // [kq][d][4]
__device__ float g_h[BATCH * DRNN];

// ---------------- prep: packed GRU weight layouts ----------------
__global__ void prep_kernel(const float* __restrict__ w_ih,
                            const float* __restrict__ w_hh,
                            const float* __restrict__ fi_w)
{
    int i = blockIdx.x * blockDim.x + threadIdx.x;
    if (i < G3 * DRNN) {                       // 196608
        int row = i >> 8;                      // 0..767 = g*256+d
        int k   = i & 255;
        int g = row >> 8, d = row & 255;
        int kq = k >> 2, j = k & 3;
        int dst = ((kq * 3 + g) * DRNN + d) * 4 + j;
        g_wihp[dst] = w_ih[i];
        g_whhp[dst] = w_hh[i];
    }
    if (i < DRNN * DRNN) {                     // 65536
        int d = i >> 8, k = i & 255;
        int kq = k >> 2, j = k & 3;
        g_fitp[(kq * DRNN + d) * 4 + j] = fi_w[i];
    }
}

// ---------------- padded frames copy ----------------
__global__ void pad_frames_kernel(const float* __restrict__ frames)
{
    int i = blockIdx.x * blockDim.x + threadIdx.x;
    if (i >= BL * FPAD) return;
    int n = i / FPAD, r = i - n * FPAD;
    int c = r / FPLANE, rr = r - c * FPLANE;
    int y = rr / 144, x = rr - y * 144;
    float v = 0.f;
    if (y >= 16 && y < 128 && x >= 16 && x < 128)
        v = frames[n * 37632 + c * 12544 + (y - 16) * 112 + (x - 16)];
    g_fpad[(size_t)i] = v;
}

// ---------------- fused conv weight: Wc = W2 o W1 ----------------
__global__ __launch_bounds__(256) void wc_gemm(const float* __restrict__ cnn1_w,
                                               const float* __restrict__ cnn_w)
{
    __shared__ float As[16][68];   // [mc][oc]
    __shared__ float Bs[16][68];   // [mc][j]
    int tid = threadIdx.x;
    int jt = blockIdx.x, tap = blockIdx.y;
    int ty16 = tap / 3, tx16 = tap - ty16 * 3;
    int tx = tid & 15, ty = tid >> 4;

    float acc[4][4];
#pragma unroll
    for (int i = 0; i < 4; i++)
#pragma unroll
        for (int j = 0; j < 4; j++) acc[i][j] = 0.f;

    int kkB = tid >> 4, j4 = (tid & 15) * 4;
    for (int mc0 = 0; mc0 < C1; mc0 += 16) {
#pragma unroll
        for (int e = 0; e < 4; e++) {
            int u = tid + e * 256;
            int oc = u >> 4, kk = u & 15;
            As[kk][oc] = cnn1_w[oc * 5184 + (mc0 + kk) * 9 + tap];
        }
        *(float4*)&Bs[kkB][j4] = *(const float4*)(cnn_w + (mc0 + kkB) * 768 + jt * 64 + j4);
        __syncthreads();
#pragma unroll
        for (int kk = 0; kk < 16; kk++) {
            float a[4], b[4];
#pragma unroll
            for (int i = 0; i < 4; i++) a[i] = As[kk][ty * 4 + i];
#pragma unroll
            for (int j = 0; j < 4; j++) b[j] = Bs[kk][tx * 4 + j];
#pragma unroll
            for (int i = 0; i < 4; i++)
#pragma unroll
                for (int j = 0; j < 4; j++) acc[i][j] += a[i] * b[j];
        }
        __syncthreads();
    }

#pragma unroll
    for (int i = 0; i < 4; i++) {
        int oc = ty * 4 + i;
#pragma unroll
        for (int jj = 0; jj < 4; jj++) {
            int j = jt * 64 + tx * 4 + jj;
            int c = j >> 8, rem = j & 255;
            int iy = rem >> 4, ix = rem & 15;
            int k = c * 2304 + (ty16 * 16 + iy) * 48 + tx16 * 16 + ix;
            g_wcT[k * DCNN + oc] = acc[i][jj];
        }
    }
}

// =====================================================================
// fused conv GEMM: M=25088, N=64, K=6912, split 6-way over K
// CTA 256 thr, tile 128x64, thread tile 8x4, KT=16
// double-buffered smem, one sync/chunk, LDG staged 2 chunks ahead
// =====================================================================
__global__ __launch_bounds__(256) void fused_gemm(void)
{
    __shared__ __align__(16) float As[2][16][132];
    __shared__ __align__(16) float Bs[2][16][68];

    int tid = threadIdx.x;
    int tx = tid & 15, ty = tid >> 4;
    int rowBase = blockIdx.x * 128;
    int ks = blockIdx.y;
    int kbase = ks * KPER;

    // A staging units: 2 per thread (each float4 = 4 k's of one row)
    int abase[2], arow[2], aq4[2];
#pragma unroll
    for (int e = 0; e < 2; e++) {
        int idx = tid + e * 256;           // 0..511
        int row = idx >> 2, q4 = idx & 3;
        int m = rowBase + row;
        int n = m / 49, p = m - n * 49;
        int py = p / 7, px = p - py * 7;
        abase[e] = n * FPAD + (py * 16) * 144 + px * 16;
        arow[e] = row;
        aq4[e] = q4;
    }
    int kkB = tid >> 4, j4 = (tid & 15) * 4;

    float acc[8][4];
#pragma unroll
    for (int i = 0; i < 8; i++)
#pragma unroll
        for (int j = 0; j < 4; j++) acc[i][j] = 0.f;

    auto chunk_off = [&](int ch) {
        int k0 = kbase + ch * 16;
        int c = k0 / 2304;
        int r = k0 - c * 2304;
        int wy = r / 48;
        int wx0 = r - wy * 48;
        return c * FPLANE + wy * 144 + wx0;
    };

    float4 ra[2], rb;
    auto stage = [&](int ch) {
        int off = chunk_off(ch);
#pragma unroll
        for (int e = 0; e < 2; e++)
            ra[e] = *(const float4*)(g_fpad + (size_t)abase[e] + off + aq4[e] * 4);
        rb = *(const float4*)(g_wcT + (size_t)(kbase + ch * 16 + kkB) * DCNN + j4);
    };
    auto commit = [&](int buf) {
#pragma unroll
        for (int e = 0; e < 2; e++) {
            int b0 = aq4[e] * 4, r = arow[e];
            As[buf][b0 + 0][r] = ra[e].x;
            As[buf][b0 + 1][r] = ra[e].y;
            As[buf][b0 + 2][r] = ra[e].z;
            As[buf][b0 + 3][r] = ra[e].w;
        }
        *(float4*)&Bs[buf][kkB][j4] = rb;
    };

    // prologue
    stage(0);
    commit(0);
    __syncthreads();
    stage(1);

    for (int ch = 0; ch < NCH; ch++) {
        int b = ch & 1;
#pragma unroll
        for (int kk = 0; kk < 16; kk++) {
            float4 a0 = *(const float4*)&As[b][kk][ty * 8];
            float4 a1 = *(const float4*)&As[b][kk][ty * 8 + 4];
            float4 b4 = *(const float4*)&Bs[b][kk][tx * 4];
            float av[8] = {a0.x, a0.y, a0.z, a0.w, a1.x, a1.y, a1.z, a1.w};
            float bv[4] = {b4.x, b4.y, b4.z, b4.w};
#pragma unroll
            for (int i = 0; i < 8; i++)
#pragma unroll
                for (int j = 0; j < 4; j++) acc[i][j] += av[i] * bv[j];
        }
        if (ch + 1 < NCH) commit(b ^ 1);
        __syncthreads();
        if (ch + 2 < NCH) stage(ch + 2);
    }

    // epilogue: write partials
    float* outp = g_yp + (size_t)ks * M1 * DCNN;
#pragma unroll
    for (int i = 0; i < 8; i++) {
        int m = rowBase + ty * 8 + i;
        *(float4*)(outp + (size_t)m * DCNN + tx * 4) =
            make_float4(acc[i][0], acc[i][1], acc[i][2], acc[i][3]);
    }
}

// ---------------- per-tap bias t[oc][tap] (parallel) ----------------
__global__ void bias_t_kernel(const float* __restrict__ cnn1_w,
                              const float* __restrict__ b1)
{
    int i = blockIdx.x * blockDim.x + threadIdx.x;
    if (i >= DCNN * 9) return;
    int oc = i / 9, tap = i - oc * 9;
    float s = 0.f;
#pragma unroll 4
    for (int mc = 0; mc < C1; mc++)
        s += cnn1_w[oc * 5184 + mc * 9 + tap] * b1[mc];
    g_t[i] = s;
}

// ---------------- bias field bb[p][oc] ----------------
__global__ void bias_bb_kernel(const float* __restrict__ b2)
{
    int p = blockIdx.x;
    int oc = threadIdx.x;
    int py = p / 7, px = p - py * 7;
    float s = b2[oc];
#pragma unroll
    for (int ty = 0; ty < 3; ty++)
#pragma unroll
        for (int tx = 0; tx < 3; tx++) {
            int ny = py + ty - 1, nx = px + tx - 1;
            if ((unsigned)ny < 7u && (unsigned)nx < 7u)
                s += g_t[oc * 9 + ty * 3 + tx];
        }
    g_bb[p * DCNN + oc] = s;
}

// ---------------- pool: sum partials + bias + relu + BN + mean --------
__global__ void pool_kernel(const float* __restrict__ bn_g,
                            const float* __restrict__ bn_b,
                            const float* __restrict__ bn_m,
                            const float* __restrict__ bn_v)
{
    int n  = blockIdx.x;
    int oc = threadIdx.x;
    const float* p0 = g_yp + (size_t)n * 49 * DCNN + oc;
    const size_t str = (size_t)M1 * DCNN;
    float s = 0.f;
#pragma unroll
    for (int p = 0; p < 49; p++) {
        float v = g_bb[p * DCNN + oc];
#pragma unroll
        for (int q = 0; q < KSPLIT; q++) v += p0[q * str + p * DCNN];
        s += fmaxf(v, 0.f);
    }
    float inv = bn_g[oc] * rsqrtf(bn_v[oc] + 1e-5f);
    g_pool[n * DCNN + oc] = (s * (1.f / 49.f) - bn_m[oc]) * inv + bn_b[oc];
}

// ---------------- state adapters + concat + an ----------------
__global__ void adapter_kernel(const float* __restrict__ x,
                               const float* __restrict__ a0_w, const float* __restrict__ a0_b,
                               const float* __restrict__ ai_w, const float* __restrict__ ai_b,
                               const float* __restrict__ an_w, const float* __restrict__ an_b)
{
    int r = blockIdx.x;
    int tid = threadIdx.x;
    __shared__ float s0[16];
    __shared__ float cat[80];

    const float* xr = x + r * 12;
    if (tid < 16) {
        float a = a0_b[tid];
#pragma unroll
        for (int j = 0; j < 12; j++) a += xr[j] * a0_w[tid * 12 + j];
        s0[tid] = fmaxf(a, 0.f);
    }
    __syncthreads();
    if (tid < 16) {
        float a = ai_b[tid];
#pragma unroll
        for (int j = 0; j < 16; j++) a += s0[j] * ai_w[tid * 16 + j];
        cat[tid] = s0[tid] + fmaxf(a, 0.f);
    }
    if (tid >= 32 && tid < 96) cat[16 + tid - 32] = g_pool[r * DCNN + tid - 32];
    __syncthreads();

    float a = an_b[tid];
#pragma unroll
    for (int j = 0; j < 80; j++) a += cat[j] * an_w[tid * 80 + j];
    g_s[r * DRNN + tid] = fmaxf(a, 0.f);
}

// ---------------- encoder input gates (packed weights) ----------------
__global__ __launch_bounds__(256) void gi_kernel(const float* __restrict__ b_ih)
{
    int blk = blockIdx.x;
    int d = threadIdx.x;
    __shared__ __align__(16) float svT[DRNN][16];

    for (int rr = 0; rr < 16; rr++) {
        int q = blk * 16 + rr;
        int t = q >> 5, b = q & 31;
        int r = b * 16 + t;
        svT[d][rr] = g_s[r * DRNN + d];
    }
    __syncthreads();

    float a0[16], a1[16], a2[16];
#pragma unroll
    for (int rr = 0; rr < 16; rr++) { a0[rr] = 0.f; a1[rr] = 0.f; a2[rr] = 0.f; }

    const float4* Wp = (const float4*)g_wihp;
    for (int kq = 0; kq < 64; kq++) {
        float4 w0 = Wp[(kq * 3 + 0) * DRNN + d];
        float4 w1 = Wp[(kq * 3 + 1) * DRNN + d];
        float4 w2 = Wp[(kq * 3 + 2) * DRNN + d];
        float w0a[4] = {w0.x, w0.y, w0.z, w0.w};
        float w1a[4] = {w1.x, w1.y, w1.z, w1.w};
        float w2a[4] = {w2.x, w2.y, w2.z, w2.w};
#pragma unroll
        for (int j = 0; j < 4; j++) {
            int k = kq * 4 + j;
            const float4* s4 = (const float4*)&svT[k][0];
#pragma unroll
            for (int c = 0; c < 4; c++) {
                float4 sv = s4[c];
                float s[4] = {sv.x, sv.y, sv.z, sv.w};
#pragma unroll
                for (int u = 0; u < 4; u++) {
                    int rr = c * 4 + u;
                    a0[rr] += s[u] * w0a[j];
                    a1[rr] += s[u] * w1a[j];
                    a2[rr] += s[u] * w2a[j];
                }
            }
        }
    }

    float bi0 = b_ih[d], bi1 = b_ih[256 + d], bi2 = b_ih[512 + d];
#pragma unroll
    for (int rr = 0; rr < 16; rr++) {
        float* o = g_gi + (size_t)(blk * 16 + rr) * G3;
        o[d] = a0[rr] + bi0;
        o[256 + d] = a1[rr] + bi1;
        o[512 + d] = a2[rr] + bi2;
    }
}

__device__ __forceinline__ float sigmoidf_(float v) { return 1.f / (1.f + expf(-v)); }

// ---------------- fused encoder (packed weights) ----------------
__global__ __launch_bounds__(256) void encoder_kernel(const float* __restrict__ b_hh)
{
    int b = blockIdx.x;
    int d = threadIdx.x;
    __shared__ __align__(16) float hs[DRNN];
    hs[d] = 0.f;
    __syncthreads();

    float bh0 = b_hh[d], bh1 = b_hh[256 + d], bh2 = b_hh[512 + d];
    const float4* Wp = (const float4*)g_whhp;

    for (int t = 0; t < LSEQ; t++) {
        float a0 = bh0, a1 = bh1, a2 = bh2;
#pragma unroll 4
        for (int kq = 0; kq < 64; kq++) {
            float4 h4 = *(const float4*)&hs[kq * 4];
            float4 w0 = Wp[(kq * 3 + 0) * DRNN + d];
            float4 w1 = Wp[(kq * 3 + 1) * DRNN + d];
            float4 w2 = Wp[(kq * 3 + 2) * DRNN + d];
            a0 += h4.x * w0.x + h4.y * w0.y + h4.z * w0.z + h4.w * w0.w;
            a1 += h4.x * w1.x + h4.y * w1.y + h4.z * w1.z + h4.w * w1.w;
            a2 += h4.x * w2.x + h4.y * w2.y + h4.z * w2.z + h4.w * w2.w;
        }
        const float* gi = g_gi + (size_t)(t * 32 + b) * G3;
        float rr = sigmoidf_(gi[d] + a0);
        float zz = sigmoidf_(gi[256 + d] + a1);
        float nn = tanhf(gi[512 + d] + rr * a2);
        float newh = (1.f - zz) * nn + zz * hs[d];
        __syncthreads();
        hs[d] = newh;
        __syncthreads();
    }
    g_h[b * DRNN + d] = hs[d];
}

// ---------------- fused decoder (packed weights) ----------------
__global__ __launch_bounds__(256) void decoder_kernel(
    const float* __restrict__ b_ih, const float* __restrict__ b_hh,
    const float* __restrict__ fi_b,
    const float* __restrict__ fn_w, const float* __restrict__ fn_b,
    float* __restrict__ out)
{
    int b = blockIdx.x;
    int d = threadIdx.x;
    __shared__ __align__(16) float hs[DRNN];
    __shared__ __align__(16) float xs[DRNN];
    __shared__ float xr[DRNN];

    float h0 = g_h[b * DRNN + d];
    hs[d] = h0;
    xs[d] = h0;
    __syncthreads();

    float bh0 = b_hh[d], bh1 = b_hh[256 + d], bh2 = b_hh[512 + d];
    float bi0 = b_ih[d], bi1 = b_ih[256 + d], bi2 = b_ih[512 + d];
    float fib = fi_b[d];
    const float4* Wh = (const float4*)g_whhp;
    const float4* Wi = (const float4*)g_wihp;
    const float4* Wf = (const float4*)g_fitp;

    for (int t = 0; t < HORIZON; t++) {
        float a0 = bh0, a1 = bh1, a2 = bh2;
        float c0 = bi0, c1 = bi1, c2 = bi2;
#pragma unroll 4
        for (int kq = 0; kq < 64; kq++) {
            float4 h4 = *(const float4*)&hs[kq * 4];
            float4 x4 = *(const float4*)&xs[kq * 4];
            float4 w0 = Wh[(kq * 3 + 0) * DRNN + d];
            float4 w1 = Wh[(kq * 3 + 1) * DRNN + d];
            float4 w2 = Wh[(kq * 3 + 2) * DRNN + d];
            float4 v0 = Wi[(kq * 3 + 0) * DRNN + d];
            float4 v1 = Wi[(kq * 3 + 1) * DRNN + d];
            float4 v2 = Wi[(kq * 3 + 2) * DRNN + d];
            a0 += h4.x * w0.x + h4.y * w0.y + h4.z * w0.z + h4.w * w0.w;
            a1 += h4.x * w1.x + h4.y * w1.y + h4.z * w1.z + h4.w * w1.w;
            a2 += h4.x * w2.x + h4.y * w2.y + h4.z * w2.z + h4.w * w2.w;
            c0 += x4.x * v0.x + x4.y * v0.y + x4.z * v0.z + x4.w * v0.w;
            c1 += x4.x * v1.x + x4.y * v1.y + x4.z * v1.z + x4.w * v1.w;
            c2 += x4.x * v2.x + x4.y * v2.y + x4.z * v2.z + x4.w * v2.w;
        }
        float rr = sigmoidf_(c0 + a0);
        float zz = sigmoidf_(c1 + a1);
        float nn = tanhf(c2 + rr * a2);
        float newh = (1.f - zz) * nn + zz * hs[d];
        __syncthreads();
        hs[d] = newh;
        __syncthreads();

        float a = fib;
#pragma unroll 4
        for (int kq = 0; kq < 64; kq++) {
            float4 h4 = *(const float4*)&hs[kq * 4];
            float4 w = Wf[kq * DRNN + d];
            a += h4.x * w.x + h4.y * w.y + h4.z * w.z + h4.w * w.w;
        }
        float v = hs[d] + fmaxf(a, 0.f);
        xr[d] = v;
        __syncthreads();
        xs[d] = v;

        if (d < 2) {
            float s = fn_b[d];
            for (int k = 0; k < DRNN; k++) s += xr[k] * fn_w[d * DRNN + k];
            out[(t * 32 + b) * 2 + d] = tanhf(s);
        }
        __syncthreads();
    }
}

// ---------------- launch ----------------
extern "C" void kernel_launch(void* const* d_in, const int* in_sizes, int n_in,
                              void* d_out, int out_size)
{
    const float* x      = (const float*)d_in[0];
    const float* frames = (const float*)d_in[1];
    const float* cnn_w  = (const float*)d_in[2];
    const float* cnn_b  = (const float*)d_in[3];
    const float* cnn1_w = (const float*)d_in[4];
    const float* cnn1_b = (const float*)d_in[5];
    const float* bn_g   = (const float*)d_in[6];
    const float* bn_b   = (const float*)d_in[7];
    const float* bn_m   = (const float*)d_in[8];
    const float* bn_v   = (const float*)d_in[9];
    const float* a0_w   = (const float*)d_in[10];
    const float* a0_b   = (const float*)d_in[11];
    const float* ai_w   = (const float*)d_in[12];
    const float* ai_b   = (const float*)d_in[13];
    const float* an_w   = (const float*)d_in[14];
    const float* an_b   = (const float*)d_in[15];
    const float* w_ih   = (const float*)d_in[16];
    const float* w_hh   = (const float*)d_in[17];
    const float* b_ih   = (const float*)d_in[18];
    const float* b_hh   = (const float*)d_in[19];
    const float* fi_w   = (const float*)d_in[20];
    const float* fi_b   = (const float*)d_in[21];
    const float* fn_w   = (const float*)d_in[22];
    const float* fn_b   = (const float*)d_in[23];
    float* out = (float*)d_out;

    prep_kernel<<<(G3 * DRNN + 255) / 256, 256>>>(w_ih, w_hh, fi_w);           // 0
    pad_frames_kernel<<<(BL * FPAD + 255) / 256, 256>>>(frames);               // 1

    dim3 gw(12, 9);
    wc_gemm<<<gw, 256>>>(cnn1_w, cnn_w);                                       // 2

    dim3 gg(M1 / 128, KSPLIT);
    fused_gemm<<<gg, 256>>>();                                                 // 3 (ncu slot)

    bias_t_kernel<<<3, 192>>>(cnn1_w, cnn_b);                                  // 4
    bias_bb_kernel<<<49, DCNN>>>(cnn1_b);                                      // 5

    pool_kernel<<<BL, DCNN>>>(bn_g, bn_b, bn_m, bn_v);                         // 6
    adapter_kernel<<<BL, DRNN>>>(x, a0_w, a0_b, ai_w, ai_b, an_w, an_b);       // 7
    gi_kernel<<<BL / 16, DRNN>>>(b_ih);                                        // 8

    encoder_kernel<<<BATCH, DRNN>>>(b_hh);                                     // 9
    decoder_kernel<<<BATCH, DRNN>>>(b_ih, b_hh, fi_b, fn_w, fn_b, out);        // 10
}

// round 9
// speedup vs baseline: 2.2547x; 1.0255x over previous
#include <cuda_runtime.h>
#include <math.h>
#include <cstdint>

// ---------------- problem constants ----------------
#define BATCH   32
#define LSEQ    16
#define BL      512
#define M1      25088        // BL * 49
#define C1      576
#define DCNN    64
#define DRNN    256
#define G3      768
#define HORIZON 10

#define KC      6912         // fused conv K = 3*48*48
#define KSPLIT  6
#define KPER    1152         // KC / KSPLIT
#define NCH     72           // KPER / 16
#define FPAD    62208        // 3*144*144
#define FPLANE  20736        // 144*144

// ---------------- scratch (device globals) ----------------
__device__ float g_fpad[(size_t)BL * FPAD];      // padded frames (512,3,144,144)
__device__ float g_wcT[KC * DCNN];               // fused conv weight, [k][oc]
__device__ float g_t[DCNN * 9];                  // per-tap bias contribution
__device__ float g_bb[49 * DCNN];                // bias field [p][oc]
__device__ float g_yp[(size_t)KSPLIT * M1 * DCNN]; // GEMM partials
__device__ float g_pool[BL * DCNN];
__device__ float g_s[BL * DRNN];
__device__ float g_gi[BL * G3];
// packed GRU weights: [kq][gate][d][4]  (kq = k/4)
__device__ float g_wihp[G3 * DRNN];
__device__ float g_whhp[G3 * DRNN];
__device__ float g_fitp[DRNN * DRNN];            // [kq][d][4]
__device__ float g_h[BATCH * DRNN];

// ---------------- prep: packed GRU weight layouts ----------------
__global__ void prep_kernel(const float* __restrict__ w_ih,
                            const float* __restrict__ w_hh,
                            const float* __restrict__ fi_w)
{
    int i = blockIdx.x * blockDim.x + threadIdx.x;
    if (i < G3 * DRNN) {
        int row = i >> 8;
        int k   = i & 255;
        int g = row >> 8, d = row & 255;
        int kq = k >> 2, j = k & 3;
        int dst = ((kq * 3 + g) * DRNN + d) * 4 + j;
        g_wihp[dst] = w_ih[i];
        g_whhp[dst] = w_hh[i];
    }
    if (i < DRNN * DRNN) {
        int d = i >> 8, k = i & 255;
        int kq = k >> 2, j = k & 3;
        g_fitp[(kq * DRNN + d) * 4 + j] = fi_w[i];
    }
}

// ---------------- padded frames copy (vectorized float4) ----------------
// grid: (108, 512) = (c*36+yg, n); block: 144 threads; thread = one float4
__global__ void pad_frames_kernel(const float* __restrict__ frames)
{
    int n  = blockIdx.y;
    int cy = blockIdx.x;            // c*36 + yg
    int c  = cy / 36;
    int yg = cy - c * 36;
    int tid = threadIdx.x;
    int dy  = tid / 36;             // 0..3
    int x4  = (tid - dy * 36) * 4;  // 0,4,...,140
    int y   = yg * 4 + dy;

    float4 v = make_float4(0.f, 0.f, 0.f, 0.f);
    if (y >= 16 && y < 128 && x4 >= 16 && x4 < 128)
        v = *(const float4*)(frames + n * 37632 + c * 12544 + (y - 16) * 112 + (x4 - 16));
    *(float4*)(g_fpad + (size_t)n * FPAD + c * FPLANE + y * 144 + x4) = v;
}

// ---------------- fused conv weight: Wc = W2 o W1 ----------------
__global__ __launch_bounds__(256) void wc_gemm(const float* __restrict__ cnn1_w,
                                               const float* __restrict__ cnn_w)
{
    __shared__ float As[16][68];   // [mc][oc]
    __shared__ float Bs[16][68];   // [mc][j]
    int tid = threadIdx.x;
    int jt = blockIdx.x, tap = blockIdx.y;
    int ty16 = tap / 3, tx16 = tap - ty16 * 3;
    int tx = tid & 15, ty = tid >> 4;

    float acc[4][4];
#pragma unroll
    for (int i = 0; i < 4; i++)
#pragma unroll
        for (int j = 0; j < 4; j++) acc[i][j] = 0.f;

    int kkB = tid >> 4, j4 = (tid & 15) * 4;
    for (int mc0 = 0; mc0 < C1; mc0 += 16) {
#pragma unroll
        for (int e = 0; e < 4; e++) {
            int u = tid + e * 256;
            int oc = u >> 4, kk = u & 15;
            As[kk][oc] = cnn1_w[oc * 5184 + (mc0 + kk) * 9 + tap];
        }
        *(float4*)&Bs[kkB][j4] = *(const float4*)(cnn_w + (mc0 + kkB) * 768 + jt * 64 + j4);
        __syncthreads();
#pragma unroll
        for (int kk = 0; kk < 16; kk++) {
            float a[4], b[4];
#pragma unroll
            for (int i = 0; i < 4; i++) a[i] = As[kk][ty * 4 + i];
#pragma unroll
            for (int j = 0; j < 4; j++) b[j] = Bs[kk][tx * 4 + j];
#pragma unroll
            for (int i = 0; i < 4; i++)
#pragma unroll
                for (int j = 0; j < 4; j++) acc[i][j] += a[i] * b[j];
        }
        __syncthreads();
    }

#pragma unroll
    for (int i = 0; i < 4; i++) {
        int oc = ty * 4 + i;
#pragma unroll
        for (int jj = 0; jj < 4; jj++) {
            int j = jt * 64 + tx * 4 + jj;
            int c = j >> 8, rem = j & 255;
            int iy = rem >> 4, ix = rem & 15;
            int k = c * 2304 + (ty16 * 16 + iy) * 48 + tx16 * 16 + ix;
            g_wcT[k * DCNN + oc] = acc[i][jj];
        }
    }
}

// =====================================================================
// fused conv GEMM: M=25088, N=64, K=6912, split 6-way over K
// CTA 128 thr, tile 128x64, thread tile 8x8, KT=16
// double-buffered smem, one sync/chunk, LDG staged 2 chunks ahead
// =====================================================================
__global__ __launch_bounds__(128) void fused_gemm(void)
{
    __shared__ __align__(16) float As[2][16][132];
    __shared__ __align__(16) float Bs[2][16][68];

    int tid = threadIdx.x;
    int tx = tid & 7, ty = tid >> 3;      // 16 row-groups x 8 col-groups
    int rowBase = blockIdx.x * 128;
    int ks = blockIdx.y;
    int kbase = ks * KPER;

    // A staging: 4 units per thread (each float4 = 4 k's of one row)
    int abase[4], arow[4], aq4[4];
#pragma unroll
    for (int e = 0; e < 4; e++) {
        int idx = tid + e * 128;           // 0..511
        int row = idx >> 2, q4 = idx & 3;
        int m = rowBase + row;
        int n = m / 49, p = m - n * 49;
        int py = p / 7, px = p - py * 7;
        abase[e] = n * FPAD + (py * 16) * 144 + px * 16;
        arow[e] = row;
        aq4[e] = q4;
    }
    // B staging: 2 units per thread
    int bkk[2], bj4[2];
#pragma unroll
    for (int e = 0; e < 2; e++) {
        int idx = tid + e * 128;           // 0..255
        bkk[e] = idx >> 4;
        bj4[e] = (idx & 15) * 4;
    }

    float acc[8][8];
#pragma unroll
    for (int i = 0; i < 8; i++)
#pragma unroll
        for (int j = 0; j < 8; j++) acc[i][j] = 0.f;

    auto chunk_off = [&](int ch) {
        int k0 = kbase + ch * 16;
        int c = k0 / 2304;
        int r = k0 - c * 2304;
        int wy = r / 48;
        int wx0 = r - wy * 48;
        return c * FPLANE + wy * 144 + wx0;
    };

    float4 ra[4], rb[2];
    auto stage = [&](int ch) {
        int off = chunk_off(ch);
#pragma unroll
        for (int e = 0; e < 4; e++)
            ra[e] = *(const float4*)(g_fpad + (size_t)abase[e] + off + aq4[e] * 4);
#pragma unroll
        for (int e = 0; e < 2; e++)
            rb[e] = *(const float4*)(g_wcT + (size_t)(kbase + ch * 16 + bkk[e]) * DCNN + bj4[e]);
    };
    auto commit = [&](int buf) {
#pragma unroll
        for (int e = 0; e < 4; e++) {
            int b0 = aq4[e] * 4, r = arow[e];
            As[buf][b0 + 0][r] = ra[e].x;
            As[buf][b0 + 1][r] = ra[e].y;
            As[buf][b0 + 2][r] = ra[e].z;
            As[buf][b0 + 3][r] = ra[e].w;
        }
#pragma unroll
        for (int e = 0; e < 2; e++)
            *(float4*)&Bs[buf][bkk[e]][bj4[e]] = rb[e];
    };

    stage(0);
    commit(0);
    __syncthreads();
    stage(1);

    for (int ch = 0; ch < NCH; ch++) {
        int b = ch & 1;
#pragma unroll
        for (int kk = 0; kk < 16; kk++) {
            float4 a0 = *(const float4*)&As[b][kk][ty * 8];
            float4 a1 = *(const float4*)&As[b][kk][ty * 8 + 4];
            float4 b0 = *(const float4*)&Bs[b][kk][tx * 8];
            float4 b1 = *(const float4*)&Bs[b][kk][tx * 8 + 4];
            float av[8] = {a0.x, a0.y, a0.z, a0.w, a1.x, a1.y, a1.z, a1.w};
            float bv[8] = {b0.x, b0.y, b0.z, b0.w, b1.x, b1.y, b1.z, b1.w};
#pragma unroll
            for (int i = 0; i < 8; i++)
#pragma unroll
                for (int j = 0; j < 8; j++) acc[i][j] += av[i] * bv[j];
        }
        if (ch + 1 < NCH) commit(b ^ 1);
        __syncthreads();
        if (ch + 2 < NCH) stage(ch + 2);
    }

    // epilogue: write partials
    float* outp = g_yp + (size_t)ks * M1 * DCNN;
#pragma unroll
    for (int i = 0; i < 8; i++) {
        int m = rowBase + ty * 8 + i;
        *(float4*)(outp + (size_t)m * DCNN + tx * 8) =
            make_float4(acc[i][0], acc[i][1], acc[i][2], acc[i][3]);
        *(float4*)(outp + (size_t)m * DCNN + tx * 8 + 4) =
            make_float4(acc[i][4], acc[i][5], acc[i][6], acc[i][7]);
    }
}

// ---------------- per-tap bias t[oc][tap] (parallel) ----------------
__global__ void bias_t_kernel(const float* __restrict__ cnn1_w,
                              const float* __restrict__ b1)
{
    int i = blockIdx.x * blockDim.x + threadIdx.x;
    if (i >= DCNN * 9) return;
    int oc = i / 9, tap = i - oc * 9;
    float s = 0.f;
#pragma unroll 4
    for (int mc = 0; mc < C1; mc++)
        s += cnn1_w[oc * 5184 + mc * 9 + tap] * b1[mc];
    g_t[i] = s;
}

// ---------------- bias field bb[p][oc] ----------------
__global__ void bias_bb_kernel(const float* __restrict__ b2)
{
    int p = blockIdx.x;
    int oc = threadIdx.x;
    int py = p / 7, px = p - py * 7;
    float s = b2[oc];
#pragma unroll
    for (int ty = 0; ty < 3; ty++)
#pragma unroll
        for (int tx = 0; tx < 3; tx++) {
            int ny = py + ty - 1, nx = px + tx - 1;
            if ((unsigned)ny < 7u && (unsigned)nx < 7u)
                s += g_t[oc * 9 + ty * 3 + tx];
        }
    g_bb[p * DCNN + oc] = s;
}

// ---------------- pool: sum partials + bias + relu + BN + mean --------
__global__ void pool_kernel(const float* __restrict__ bn_g,
                            const float* __restrict__ bn_b,
                            const float* __restrict__ bn_m,
                            const float* __restrict__ bn_v)
{
    int n  = blockIdx.x;
    int oc = threadIdx.x;
    const float* p0 = g_yp + (size_t)n * 49 * DCNN + oc;
    const size_t str = (size_t)M1 * DCNN;
    float s = 0.f;
#pragma unroll
    for (int p = 0; p < 49; p++) {
        float v = g_bb[p * DCNN + oc];
#pragma unroll
        for (int q = 0; q < KSPLIT; q++) v += p0[q * str + p * DCNN];
        s += fmaxf(v, 0.f);
    }
    float inv = bn_g[oc] * rsqrtf(bn_v[oc] + 1e-5f);
    g_pool[n * DCNN + oc] = (s * (1.f / 49.f) - bn_m[oc]) * inv + bn_b[oc];
}

// ---------------- state adapters + concat + an ----------------
__global__ void adapter_kernel(const float* __restrict__ x,
                               const float* __restrict__ a0_w, const float* __restrict__ a0_b,
                               const float* __restrict__ ai_w, const float* __restrict__ ai_b,
                               const float* __restrict__ an_w, const float* __restrict__ an_b)
{
    int r = blockIdx.x;
    int tid = threadIdx.x;
    __shared__ float s0[16];
    __shared__ float cat[80];

    const float* xr = x + r * 12;
    if (tid < 16) {
        float a = a0_b[tid];
#pragma unroll
        for (int j = 0; j < 12; j++) a += xr[j] * a0_w[tid * 12 + j];
        s0[tid] = fmaxf(a, 0.f);
    }
    __syncthreads();
    if (tid < 16) {
        float a = ai_b[tid];
#pragma unroll
        for (int j = 0; j < 16; j++) a += s0[j] * ai_w[tid * 16 + j];
        cat[tid] = s0[tid] + fmaxf(a, 0.f);
    }
    if (tid >= 32 && tid < 96) cat[16 + tid - 32] = g_pool[r * DCNN + tid - 32];
    __syncthreads();

    float a = an_b[tid];
#pragma unroll
    for (int j = 0; j < 80; j++) a += cat[j] * an_w[tid * 80 + j];
    g_s[r * DRNN + tid] = fmaxf(a, 0.f);
}

// ---------------- encoder input gates (packed weights) ----------------
__global__ __launch_bounds__(256) void gi_kernel(const float* __restrict__ b_ih)
{
    int blk = blockIdx.x;
    int d = threadIdx.x;
    __shared__ __align__(16) float svT[DRNN][16];

    for (int rr = 0; rr < 16; rr++) {
        int q = blk * 16 + rr;
        int t = q >> 5, b = q & 31;
        int r = b * 16 + t;
        svT[d][rr] = g_s[r * DRNN + d];
    }
    __syncthreads();

    float a0[16], a1[16], a2[16];
#pragma unroll
    for (int rr = 0; rr < 16; rr++) { a0[rr] = 0.f; a1[rr] = 0.f; a2[rr] = 0.f; }

    const float4* Wp = (const float4*)g_wihp;
    for (int kq = 0; kq < 64; kq++) {
        float4 w0 = Wp[(kq * 3 + 0) * DRNN + d];
        float4 w1 = Wp[(kq * 3 + 1) * DRNN + d];
        float4 w2 = Wp[(kq * 3 + 2) * DRNN + d];
        float w0a[4] = {w0.x, w0.y, w0.z, w0.w};
        float w1a[4] = {w1.x, w1.y, w1.z, w1.w};
        float w2a[4] = {w2.x, w2.y, w2.z, w2.w};
#pragma unroll
        for (int j = 0; j < 4; j++) {
            int k = kq * 4 + j;
            const float4* s4 = (const float4*)&svT[k][0];
#pragma unroll
            for (int c = 0; c < 4; c++) {
                float4 sv = s4[c];
                float s[4] = {sv.x, sv.y, sv.z, sv.w};
#pragma unroll
                for (int u = 0; u < 4; u++) {
                    int rr = c * 4 + u;
                    a0[rr] += s[u] * w0a[j];
                    a1[rr] += s[u] * w1a[j];
                    a2[rr] += s[u] * w2a[j];
                }
            }
        }
    }

    float bi0 = b_ih[d], bi1 = b_ih[256 + d], bi2 = b_ih[512 + d];
#pragma unroll
    for (int rr = 0; rr < 16; rr++) {
        float* o = g_gi + (size_t)(blk * 16 + rr) * G3;
        o[d] = a0[rr] + bi0;
        o[256 + d] = a1[rr] + bi1;
        o[512 + d] = a2[rr] + bi2;
    }
}

__device__ __forceinline__ float sigmoidf_(float v) { return 1.f / (1.f + expf(-v)); }

// ---------------- fused encoder (packed weights) ----------------
__global__ __launch_bounds__(256) void encoder_kernel(const float* __restrict__ b_hh)
{
    int b = blockIdx.x;
    int d = threadIdx.x;
    __shared__ __align__(16) float hs[DRNN];
    hs[d] = 0.f;
    __syncthreads();

    float bh0 = b_hh[d], bh1 = b_hh[256 + d], bh2 = b_hh[512 + d];
    const float4* Wp = (const float4*)g_whhp;

    for (int t = 0; t < LSEQ; t++) {
        float a0 = bh0, a1 = bh1, a2 = bh2;
#pragma unroll 4
        for (int kq = 0; kq < 64; kq++) {
            float4 h4 = *(const float4*)&hs[kq * 4];
            float4 w0 = Wp[(kq * 3 + 0) * DRNN + d];
            float4 w1 = Wp[(kq * 3 + 1) * DRNN + d];
            float4 w2 = Wp[(kq * 3 + 2) * DRNN + d];
            a0 += h4.x * w0.x + h4.y * w0.y + h4.z * w0.z + h4.w * w0.w;
            a1 += h4.x * w1.x + h4.y * w1.y + h4.z * w1.z + h4.w * w1.w;
            a2 += h4.x * w2.x + h4.y * w2.y + h4.z * w2.z + h4.w * w2.w;
        }
        const float* gi = g_gi + (size_t)(t * 32 + b) * G3;
        float rr = sigmoidf_(gi[d] + a0);
        float zz = sigmoidf_(gi[256 + d] + a1);
        float nn = tanhf(gi[512 + d] + rr * a2);
        float newh = (1.f - zz) * nn + zz * hs[d];
        __syncthreads();
        hs[d] = newh;
        __syncthreads();
    }
    g_h[b * DRNN + d] = hs[d];
}

// ---------------- fused decoder (packed weights) ----------------
__global__ __launch_bounds__(256) void decoder_kernel(
    const float* __restrict__ b_ih, const float* __restrict__ b_hh,
    const float* __restrict__ fi_b,
    const float* __restrict__ fn_w, const float* __restrict__ fn_b,
    float* __restrict__ out)
{
    int b = blockIdx.x;
    int d = threadIdx.x;
    __shared__ __align__(16) float hs[DRNN];
    __shared__ __align__(16) float xs[DRNN];
    __shared__ float xr[DRNN];

    float h0 = g_h[b * DRNN + d];
    hs[d] = h0;
    xs[d] = h0;
    __syncthreads();

    float bh0 = b_hh[d], bh1 = b_hh[256 + d], bh2 = b_hh[512 + d];
    float bi0 = b_ih[d], bi1 = b_ih[256 + d], bi2 = b_ih[512 + d];
    float fib = fi_b[d];
    const float4* Wh = (const float4*)g_whhp;
    const float4* Wi = (const float4*)g_wihp;
    const float4* Wf = (const float4*)g_fitp;

    for (int t = 0; t < HORIZON; t++) {
        float a0 = bh0, a1 = bh1, a2 = bh2;
        float c0 = bi0, c1 = bi1, c2 = bi2;
#pragma unroll 4
        for (int kq = 0; kq < 64; kq++) {
            float4 h4 = *(const float4*)&hs[kq * 4];
            float4 x4 = *(const float4*)&xs[kq * 4];
            float4 w0 = Wh[(kq * 3 + 0) * DRNN + d];
            float4 w1 = Wh[(kq * 3 + 1) * DRNN + d];
            float4 w2 = Wh[(kq * 3 + 2) * DRNN + d];
            float4 v0 = Wi[(kq * 3 + 0) * DRNN + d];
            float4 v1 = Wi[(kq * 3 + 1) * DRNN + d];
            float4 v2 = Wi[(kq * 3 + 2) * DRNN + d];
            a0 += h4.x * w0.x + h4.y * w0.y + h4.z * w0.z + h4.w * w0.w;
            a1 += h4.x * w1.x + h4.y * w1.y + h4.z * w1.z + h4.w * w1.w;
            a2 += h4.x * w2.x + h4.y * w2.y + h4.z * w2.z + h4.w * w2.w;
            c0 += x4.x * v0.x + x4.y * v0.y + x4.z * v0.z + x4.w * v0.w;
            c1 += x4.x * v1.x + x4.y * v1.y + x4.z * v1.z + x4.w * v1.w;
            c2 += x4.x * v2.x + x4.y * v2.y + x4.z * v2.z + x4.w * v2.w;
        }
        float rr = sigmoidf_(c0 + a0);
        float zz = sigmoidf_(c1 + a1);
        float nn = tanhf(c2 + rr * a2);
        float newh = (1.f - zz) * nn + zz * hs[d];
        __syncthreads();
        hs[d] = newh;
        __syncthreads();

        float a = fib;
#pragma unroll 4
        for (int kq = 0; kq < 64; kq++) {
            float4 h4 = *(const float4*)&hs[kq * 4];
            float4 w = Wf[kq * DRNN + d];
            a += h4.x * w.x + h4.y * w.y + h4.z * w.z + h4.w * w.w;
        }
        float v = hs[d] + fmaxf(a, 0.f);
        xr[d] = v;
        __syncthreads();
        xs[d] = v;

        if (d < 2) {
            float s = fn_b[d];
            for (int k = 0; k < DRNN; k++) s += xr[k] * fn_w[d * DRNN + k];
            out[(t * 32 + b) * 2 + d] = tanhf(s);
        }
        __syncthreads();
    }
}

// ---------------- launch ----------------
extern "C" void kernel_launch(void* const* d_in, const int* in_sizes, int n_in,
                              void* d_out, int out_size)
{
    const float* x      = (const float*)d_in[0];
    const float* frames = (const float*)d_in[1];
    const float* cnn_w  = (const float*)d_in[2];
    const float* cnn_b  = (const float*)d_in[3];
    const float* cnn1_w = (const float*)d_in[4];
    const float* cnn1_b = (const float*)d_in[5];
    const float* bn_g   = (const float*)d_in[6];
    const float* bn_b   = (const float*)d_in[7];
    const float* bn_m   = (const float*)d_in[8];
    const float* bn_v   = (const float*)d_in[9];
    const float* a0_w   = (const float*)d_in[10];
    const float* a0_b   = (const float*)d_in[11];
    const float* ai_w   = (const float*)d_in[12];
    const float* ai_b   = (const float*)d_in[13];
    const float* an_w   = (const float*)d_in[14];
    const float* an_b   = (const float*)d_in[15];
    const float* w_ih   = (const float*)d_in[16];
    const float* w_hh   = (const float*)d_in[17];
    const float* b_ih   = (const float*)d_in[18];
    const float* b_hh   = (const float*)d_in[19];
    const float* fi_w   = (const float*)d_in[20];
    const float* fi_b   = (const float*)d_in[21];
    const float* fn_w   = (const float*)d_in[22];
    const float* fn_b   = (const float*)d_in[23];
    float* out = (float*)d_out;

    prep_kernel<<<(G3 * DRNN + 255) / 256, 256>>>(w_ih, w_hh, fi_w);

    dim3 gp(108, BL);
    pad_frames_kernel<<<gp, 144>>>(frames);

    dim3 gw(12, 9);
    wc_gemm<<<gw, 256>>>(cnn1_w, cnn_w);

    dim3 gg(M1 / 128, KSPLIT);
    fused_gemm<<<gg, 128>>>();

    bias_t_kernel<<<3, 192>>>(cnn1_w, cnn_b);
    bias_bb_kernel<<<49, DCNN>>>(cnn1_b);

    pool_kernel<<<BL, DCNN>>>(bn_g, bn_b, bn_m, bn_v);
    adapter_kernel<<<BL, DRNN>>>(x, a0_w, a0_b, ai_w, ai_b, an_w, an_b);
    gi_kernel<<<BL / 16, DRNN>>>(b_ih);

    encoder_kernel<<<BATCH, DRNN>>>(b_hh);
    decoder_kernel<<<BATCH, DRNN>>>(b_ih, b_hh, fi_b, fn_w, fn_b, out);
}

// round 10
// speedup vs baseline: 2.5664x; 1.1382x over previous
#include <cuda_runtime.h>
#include <math.h>
#include <cstdint>

// ---------------- problem constants ----------------
#define BATCH   32
#define LSEQ    16
#define BL      512
#define M1      25088        // BL * 49
#define C1      576
#define DCNN    64
#define DRNN    256
#define G3      768
#define HORIZON 10

#define KC      6912         // fused conv K = 3*48*48
#define KSPLIT  6
#define KPER    1152         // KC / KSPLIT
#define NCH     72           // KPER / 16
#define FPAD    62208        // 3*144*144
#define FPLANE  20736        // 144*144

// ---------------- scratch (device globals) ----------------
__device__ float g_fpad[(size_t)BL * FPAD];
__device__ float g_wcT[KC * DCNN];
__device__ float g_t[DCNN * 9];
__device__ float g_bb[49 * DCNN];
__device__ float g_yp[(size_t)KSPLIT * M1 * DCNN];
__device__ float g_pool[BL * DCNN];
__device__ float g_s[BL * DRNN];
__device__ float g_gi[BL * G3];
__device__ float g_wihp[G3 * DRNN];   // [kq][gate][d][4]
__device__ float g_whhp[G3 * DRNN];
__device__ float g_fitp[DRNN * DRNN]; // [kq][d][4]
__device__ float g_h[BATCH * DRNN];

// ---------------- prep: packed GRU weights + per-tap bias ----------------
__global__ void prep_kernel(const float* __restrict__ w_ih,
                            const float* __restrict__ w_hh,
                            const float* __restrict__ fi_w,
                            const float* __restrict__ cnn1_w,
                            const float* __restrict__ b1)
{
    int i = blockIdx.x * blockDim.x + threadIdx.x;
    if (i < G3 * DRNN) {
        int row = i >> 8;
        int k   = i & 255;
        int g = row >> 8, d = row & 255;
        int kq = k >> 2, j = k & 3;
        int dst = ((kq * 3 + g) * DRNN + d) * 4 + j;
        g_wihp[dst] = w_ih[i];
        g_whhp[dst] = w_hh[i];
    }
    if (i < DRNN * DRNN) {
        int d = i >> 8, k = i & 255;
        int kq = k >> 2, j = k & 3;
        g_fitp[(kq * DRNN + d) * 4 + j] = fi_w[i];
    }
    if (i < DCNN * 9) {                    // bias_t
        int oc = i / 9, tap = i - oc * 9;
        float s = 0.f;
#pragma unroll 4
        for (int mc = 0; mc < C1; mc++)
            s += cnn1_w[oc * 5184 + mc * 9 + tap] * b1[mc];
        g_t[i] = s;
    }
}

// ---------------- padded frames copy (float4) ----------------
__global__ void pad_frames_kernel(const float* __restrict__ frames)
{
    int n  = blockIdx.y;
    int cy = blockIdx.x;            // c*36 + yg
    int c  = cy / 36;
    int yg = cy - c * 36;
    int tid = threadIdx.x;
    int dy  = tid / 36;
    int x4  = (tid - dy * 36) * 4;
    int y   = yg * 4 + dy;

    float4 v = make_float4(0.f, 0.f, 0.f, 0.f);
    if (y >= 16 && y < 128 && x4 >= 16 && x4 < 128)
        v = *(const float4*)(frames + n * 37632 + c * 12544 + (y - 16) * 112 + (x4 - 16));
    *(float4*)(g_fpad + (size_t)n * FPAD + c * FPLANE + y * 144 + x4) = v;
}

// ---------------- fused conv weight: Wc = W2 o W1 ----------------
__global__ __launch_bounds__(256) void wc_gemm(const float* __restrict__ cnn1_w,
                                               const float* __restrict__ cnn_w)
{
    __shared__ float As[16][68];
    __shared__ float Bs[16][68];
    int tid = threadIdx.x;
    int jt = blockIdx.x, tap = blockIdx.y;
    int ty16 = tap / 3, tx16 = tap - ty16 * 3;
    int tx = tid & 15, ty = tid >> 4;

    float acc[4][4];
#pragma unroll
    for (int i = 0; i < 4; i++)
#pragma unroll
        for (int j = 0; j < 4; j++) acc[i][j] = 0.f;

    int kkB = tid >> 4, j4 = (tid & 15) * 4;
    for (int mc0 = 0; mc0 < C1; mc0 += 16) {
#pragma unroll
        for (int e = 0; e < 4; e++) {
            int u = tid + e * 256;
            int oc = u >> 4, kk = u & 15;
            As[kk][oc] = cnn1_w[oc * 5184 + (mc0 + kk) * 9 + tap];
        }
        *(float4*)&Bs[kkB][j4] = *(const float4*)(cnn_w + (mc0 + kkB) * 768 + jt * 64 + j4);
        __syncthreads();
#pragma unroll
        for (int kk = 0; kk < 16; kk++) {
            float a[4], b[4];
#pragma unroll
            for (int i = 0; i < 4; i++) a[i] = As[kk][ty * 4 + i];
#pragma unroll
            for (int j = 0; j < 4; j++) b[j] = Bs[kk][tx * 4 + j];
#pragma unroll
            for (int i = 0; i < 4; i++)
#pragma unroll
                for (int j = 0; j < 4; j++) acc[i][j] += a[i] * b[j];
        }
        __syncthreads();
    }

#pragma unroll
    for (int i = 0; i < 4; i++) {
        int oc = ty * 4 + i;
#pragma unroll
        for (int jj = 0; jj < 4; jj++) {
            int j = jt * 64 + tx * 4 + jj;
            int c = j >> 8, rem = j & 255;
            int iy = rem >> 4, ix = rem & 15;
            int k = c * 2304 + (ty16 * 16 + iy) * 48 + tx16 * 16 + ix;
            g_wcT[k * DCNN + oc] = acc[i][jj];
        }
    }
}

// =====================================================================
// fused conv GEMM: M=25088, N=64, K=6912, KSPLIT=6
// 256 thr, tile 128x64, thread tile 8x4; warp shaped ty:4 x tx:8
// =====================================================================
__global__ __launch_bounds__(256) void fused_gemm(void)
{
    __shared__ __align__(16) float As[2][16][132];
    __shared__ __align__(16) float Bs[2][16][68];

    int tid = threadIdx.x;
    int w = tid >> 5, l = tid & 31;
    int ty = (w >> 1) * 4 + (l >> 3);     // 0..15
    int tx = (w & 1) * 8 + (l & 7);       // 0..15
    int rowBase = blockIdx.x * 128;
    int ks = blockIdx.y;
    int kbase = ks * KPER;

    int abase[2], arow[2], aq4[2];
#pragma unroll
    for (int e = 0; e < 2; e++) {
        int idx = tid + e * 256;           // 0..511
        int row = idx >> 2, q4 = idx & 3;
        int m = rowBase + row;
        int n = m / 49, p = m - n * 49;
        int py = p / 7, px = p - py * 7;
        abase[e] = n * FPAD + (py * 16) * 144 + px * 16;
        arow[e] = row;
        aq4[e] = q4;
    }
    int kkB = tid >> 4, j4 = (tid & 15) * 4;

    float acc[8][4];
#pragma unroll
    for (int i = 0; i < 8; i++)
#pragma unroll
        for (int j = 0; j < 4; j++) acc[i][j] = 0.f;

    auto chunk_off = [&](int ch) {
        int k0 = kbase + ch * 16;
        int c = k0 / 2304;
        int r = k0 - c * 2304;
        int wy = r / 48;
        int wx0 = r - wy * 48;
        return c * FPLANE + wy * 144 + wx0;
    };

    float4 ra[2], rb;
    auto stage = [&](int ch) {
        int off = chunk_off(ch);
#pragma unroll
        for (int e = 0; e < 2; e++)
            ra[e] = *(const float4*)(g_fpad + (size_t)abase[e] + off + aq4[e] * 4);
        rb = *(const float4*)(g_wcT + (size_t)(kbase + ch * 16 + kkB) * DCNN + j4);
    };
    auto commit = [&](int buf) {
#pragma unroll
        for (int e = 0; e < 2; e++) {
            int b0 = aq4[e] * 4, r = arow[e];
            As[buf][b0 + 0][r] = ra[e].x;
            As[buf][b0 + 1][r] = ra[e].y;
            As[buf][b0 + 2][r] = ra[e].z;
            As[buf][b0 + 3][r] = ra[e].w;
        }
        *(float4*)&Bs[buf][kkB][j4] = rb;
    };

    stage(0);
    commit(0);
    __syncthreads();
    stage(1);

    for (int ch = 0; ch < NCH; ch++) {
        int b = ch & 1;
#pragma unroll
        for (int kk = 0; kk < 16; kk++) {
            float4 a0 = *(const float4*)&As[b][kk][ty * 8];
            float4 a1 = *(const float4*)&As[b][kk][ty * 8 + 4];
            float4 b4 = *(const float4*)&Bs[b][kk][tx * 4];
            float av[8] = {a0.x, a0.y, a0.z, a0.w, a1.x, a1.y, a1.z, a1.w};
            float bv[4] = {b4.x, b4.y, b4.z, b4.w};
#pragma unroll
            for (int i = 0; i < 8; i++)
#pragma unroll
                for (int j = 0; j < 4; j++) acc[i][j] += av[i] * bv[j];
        }
        if (ch + 1 < NCH) commit(b ^ 1);
        __syncthreads();
        if (ch + 2 < NCH) stage(ch + 2);
    }

    float* outp = g_yp + (size_t)ks * M1 * DCNN;
#pragma unroll
    for (int i = 0; i < 8; i++) {
        int m = rowBase + ty * 8 + i;
        *(float4*)(outp + (size_t)m * DCNN + tx * 4) =
            make_float4(acc[i][0], acc[i][1], acc[i][2], acc[i][3]);
    }
}

// ---------------- bias field bb[p][oc] ----------------
__global__ void bias_bb_kernel(const float* __restrict__ b2)
{
    int p = blockIdx.x;
    int oc = threadIdx.x;
    int py = p / 7, px = p - py * 7;
    float s = b2[oc];
#pragma unroll
    for (int ty = 0; ty < 3; ty++)
#pragma unroll
        for (int tx = 0; tx < 3; tx++) {
            int ny = py + ty - 1, nx = px + tx - 1;
            if ((unsigned)ny < 7u && (unsigned)nx < 7u)
                s += g_t[oc * 9 + ty * 3 + tx];
        }
    g_bb[p * DCNN + oc] = s;
}

// ---------------- pool: 4-way p-parallel + smem reduce ----------------
__global__ __launch_bounds__(256) void pool_kernel(
    const float* __restrict__ bn_g, const float* __restrict__ bn_b,
    const float* __restrict__ bn_m, const float* __restrict__ bn_v)
{
    __shared__ float part[4][DCNN];
    int n  = blockIdx.x;
    int tid = threadIdx.x;
    int pg = tid >> 6;            // 0..3
    int oc = tid & 63;
    const float* p0 = g_yp + (size_t)n * 49 * DCNN + oc;
    const size_t str = (size_t)M1 * DCNN;
    float s = 0.f;
    for (int p = pg; p < 49; p += 4) {
        float v = g_bb[p * DCNN + oc];
#pragma unroll
        for (int q = 0; q < KSPLIT; q++) v += p0[q * str + p * DCNN];
        s += fmaxf(v, 0.f);
    }
    part[pg][oc] = s;
    __syncthreads();
    if (tid < DCNN) {
        float t = part[0][tid] + part[1][tid] + part[2][tid] + part[3][tid];
        float inv = bn_g[tid] * rsqrtf(bn_v[tid] + 1e-5f);
        g_pool[n * DCNN + tid] = (t * (1.f / 49.f) - bn_m[tid]) * inv + bn_b[tid];
    }
}

// ---------------- state adapters + concat + an ----------------
__global__ void adapter_kernel(const float* __restrict__ x,
                               const float* __restrict__ a0_w, const float* __restrict__ a0_b,
                               const float* __restrict__ ai_w, const float* __restrict__ ai_b,
                               const float* __restrict__ an_w, const float* __restrict__ an_b)
{
    int r = blockIdx.x;
    int tid = threadIdx.x;
    __shared__ float s0[16];
    __shared__ float cat[80];

    const float* xr = x + r * 12;
    if (tid < 16) {
        float a = a0_b[tid];
#pragma unroll
        for (int j = 0; j < 12; j++) a += xr[j] * a0_w[tid * 12 + j];
        s0[tid] = fmaxf(a, 0.f);
    }
    __syncthreads();
    if (tid < 16) {
        float a = ai_b[tid];
#pragma unroll
        for (int j = 0; j < 16; j++) a += s0[j] * ai_w[tid * 16 + j];
        cat[tid] = s0[tid] + fmaxf(a, 0.f);
    }
    if (tid >= 32 && tid < 96) cat[16 + tid - 32] = g_pool[r * DCNN + tid - 32];
    __syncthreads();

    float a = an_b[tid];
#pragma unroll
    for (int j = 0; j < 80; j++) a += cat[j] * an_w[tid * 80 + j];
    g_s[r * DRNN + tid] = fmaxf(a, 0.f);
}

// ---------------- encoder input gates ----------------
__global__ __launch_bounds__(256) void gi_kernel(const float* __restrict__ b_ih)
{
    int blk = blockIdx.x;
    int d = threadIdx.x;
    __shared__ __align__(16) float svT[DRNN][16];

    for (int rr = 0; rr < 16; rr++) {
        int q = blk * 16 + rr;
        int t = q >> 5, b = q & 31;
        int r = b * 16 + t;
        svT[d][rr] = g_s[r * DRNN + d];
    }
    __syncthreads();

    float a0[16], a1[16], a2[16];
#pragma unroll
    for (int rr = 0; rr < 16; rr++) { a0[rr] = 0.f; a1[rr] = 0.f; a2[rr] = 0.f; }

    const float4* Wp = (const float4*)g_wihp;
    for (int kq = 0; kq < 64; kq++) {
        float4 w0 = Wp[(kq * 3 + 0) * DRNN + d];
        float4 w1 = Wp[(kq * 3 + 1) * DRNN + d];
        float4 w2 = Wp[(kq * 3 + 2) * DRNN + d];
        float w0a[4] = {w0.x, w0.y, w0.z, w0.w};
        float w1a[4] = {w1.x, w1.y, w1.z, w1.w};
        float w2a[4] = {w2.x, w2.y, w2.z, w2.w};
#pragma unroll
        for (int j = 0; j < 4; j++) {
            int k = kq * 4 + j;
            const float4* s4 = (const float4*)&svT[k][0];
#pragma unroll
            for (int c = 0; c < 4; c++) {
                float4 sv = s4[c];
                float s[4] = {sv.x, sv.y, sv.z, sv.w};
#pragma unroll
                for (int u = 0; u < 4; u++) {
                    int rr = c * 4 + u;
                    a0[rr] += s[u] * w0a[j];
                    a1[rr] += s[u] * w1a[j];
                    a2[rr] += s[u] * w2a[j];
                }
            }
        }
    }

    float bi0 = b_ih[d], bi1 = b_ih[256 + d], bi2 = b_ih[512 + d];
#pragma unroll
    for (int rr = 0; rr < 16; rr++) {
        float* o = g_gi + (size_t)(blk * 16 + rr) * G3;
        o[d] = a0[rr] + bi0;
        o[256 + d] = a1[rr] + bi1;
        o[512 + d] = a2[rr] + bi2;
    }
}

__device__ __forceinline__ float sigmoidf_(float v) { return 1.f / (1.f + expf(-v)); }

// ---------------- fused encoder: 512 threads, split-K ----------------
__global__ __launch_bounds__(512) void encoder_kernel(const float* __restrict__ b_hh)
{
    int b = blockIdx.x;
    int tid = threadIdx.x;
    int half = tid >> 8;          // 0 or 1
    int d = tid & 255;
    __shared__ __align__(16) float hs[DRNN];
    __shared__ float part[3][DRNN];

    if (half == 0) hs[d] = 0.f;
    __syncthreads();

    float bh0 = b_hh[d], bh1 = b_hh[256 + d], bh2 = b_hh[512 + d];
    const float4* Wp = (const float4*)g_whhp;
    int kq0 = half * 32;

    for (int t = 0; t < LSEQ; t++) {
        float a0 = 0.f, a1 = 0.f, a2 = 0.f;
#pragma unroll 4
        for (int kq = kq0; kq < kq0 + 32; kq++) {
            float4 h4 = *(const float4*)&hs[kq * 4];
            float4 w0 = Wp[(kq * 3 + 0) * DRNN + d];
            float4 w1 = Wp[(kq * 3 + 1) * DRNN + d];
            float4 w2 = Wp[(kq * 3 + 2) * DRNN + d];
            a0 += h4.x * w0.x + h4.y * w0.y + h4.z * w0.z + h4.w * w0.w;
            a1 += h4.x * w1.x + h4.y * w1.y + h4.z * w1.z + h4.w * w1.w;
            a2 += h4.x * w2.x + h4.y * w2.y + h4.z * w2.z + h4.w * w2.w;
        }
        if (half == 1) { part[0][d] = a0; part[1][d] = a1; part[2][d] = a2; }
        float oldh = hs[d];
        __syncthreads();
        if (half == 0) {
            a0 += part[0][d] + bh0;
            a1 += part[1][d] + bh1;
            a2 += part[2][d] + bh2;
            const float* gi = g_gi + (size_t)(t * 32 + b) * G3;
            float rr = sigmoidf_(gi[d] + a0);
            float zz = sigmoidf_(gi[256 + d] + a1);
            float nn = tanhf(gi[512 + d] + rr * a2);
            hs[d] = (1.f - zz) * nn + zz * oldh;
        }
        __syncthreads();
    }
    if (half == 0) g_h[b * DRNN + d] = hs[d];
}

// ---------------- fused decoder: 512 threads, split-K ----------------
__global__ __launch_bounds__(512) void decoder_kernel(
    const float* __restrict__ b_ih, const float* __restrict__ b_hh,
    const float* __restrict__ fi_b,
    const float* __restrict__ fn_w, const float* __restrict__ fn_b,
    float* __restrict__ out)
{
    int b = blockIdx.x;
    int tid = threadIdx.x;
    int half = tid >> 8;
    int d = tid & 255;
    __shared__ __align__(16) float hs[DRNN];
    __shared__ __align__(16) float xs[DRNN];
    __shared__ float xr[DRNN];
    __shared__ float part[6][DRNN];
    __shared__ float partf[DRNN];

    if (half == 0) {
        float h0 = g_h[b * DRNN + d];
        hs[d] = h0;
        xs[d] = h0;
    }
    __syncthreads();

    float bh0 = b_hh[d], bh1 = b_hh[256 + d], bh2 = b_hh[512 + d];
    float bi0 = b_ih[d], bi1 = b_ih[256 + d], bi2 = b_ih[512 + d];
    float fib = fi_b[d];
    const float4* Wh = (const float4*)g_whhp;
    const float4* Wi = (const float4*)g_wihp;
    const float4* Wf = (const float4*)g_fitp;
    int kq0 = half * 32;

    for (int t = 0; t < HORIZON; t++) {
        float a0 = 0.f, a1 = 0.f, a2 = 0.f;
        float c0 = 0.f, c1 = 0.f, c2 = 0.f;
#pragma unroll 4
        for (int kq = kq0; kq < kq0 + 32; kq++) {
            float4 h4 = *(const float4*)&hs[kq * 4];
            float4 x4 = *(const float4*)&xs[kq * 4];
            float4 w0 = Wh[(kq * 3 + 0) * DRNN + d];
            float4 w1 = Wh[(kq * 3 + 1) * DRNN + d];
            float4 w2 = Wh[(kq * 3 + 2) * DRNN + d];
            float4 v0 = Wi[(kq * 3 + 0) * DRNN + d];
            float4 v1 = Wi[(kq * 3 + 1) * DRNN + d];
            float4 v2 = Wi[(kq * 3 + 2) * DRNN + d];
            a0 += h4.x * w0.x + h4.y * w0.y + h4.z * w0.z + h4.w * w0.w;
            a1 += h4.x * w1.x + h4.y * w1.y + h4.z * w1.z + h4.w * w1.w;
            a2 += h4.x * w2.x + h4.y * w2.y + h4.z * w2.z + h4.w * w2.w;
            c0 += x4.x * v0.x + x4.y * v0.y + x4.z * v0.z + x4.w * v0.w;
            c1 += x4.x * v1.x + x4.y * v1.y + x4.z * v1.z + x4.w * v1.w;
            c2 += x4.x * v2.x + x4.y * v2.y + x4.z * v2.z + x4.w * v2.w;
        }
        if (half == 1) {
            part[0][d] = a0; part[1][d] = a1; part[2][d] = a2;
            part[3][d] = c0; part[4][d] = c1; part[5][d] = c2;
        }
        float oldh = hs[d];
        __syncthreads();
        if (half == 0) {
            a0 += part[0][d] + bh0;
            a1 += part[1][d] + bh1;
            a2 += part[2][d] + bh2;
            c0 += part[3][d] + bi0;
            c1 += part[4][d] + bi1;
            c2 += part[5][d] + bi2;
            float rr = sigmoidf_(c0 + a0);
            float zz = sigmoidf_(c1 + a1);
            float nn = tanhf(c2 + rr * a2);
            hs[d] = (1.f - zz) * nn + zz * oldh;
        }
        __syncthreads();

        // residual fi (split-K)
        float a = 0.f;
#pragma unroll 4
        for (int kq = kq0; kq < kq0 + 32; kq++) {
            float4 h4 = *(const float4*)&hs[kq * 4];
            float4 wv = Wf[kq * DRNN + d];
            a += h4.x * wv.x + h4.y * wv.y + h4.z * wv.z + h4.w * wv.w;
        }
        if (half == 1) partf[d] = a;
        __syncthreads();
        if (half == 0) {
            a += partf[d] + fib;
            float v = hs[d] + fmaxf(a, 0.f);
            xr[d] = v;
            xs[d] = v;
        }
        __syncthreads();

        if (tid < 2) {
            float s = fn_b[tid];
            for (int k = 0; k < DRNN; k++) s += xr[k] * fn_w[tid * DRNN + k];
            out[(t * 32 + b) * 2 + tid] = tanhf(s);
        }
        __syncthreads();
    }
}

// ---------------- launch ----------------
extern "C" void kernel_launch(void* const* d_in, const int* in_sizes, int n_in,
                              void* d_out, int out_size)
{
    const float* x      = (const float*)d_in[0];
    const float* frames = (const float*)d_in[1];
    const float* cnn_w  = (const float*)d_in[2];
    const float* cnn_b  = (const float*)d_in[3];
    const float* cnn1_w = (const float*)d_in[4];
    const float* cnn1_b = (const float*)d_in[5];
    const float* bn_g   = (const float*)d_in[6];
    const float* bn_b   = (const float*)d_in[7];
    const float* bn_m   = (const float*)d_in[8];
    const float* bn_v   = (const float*)d_in[9];
    const float* a0_w   = (const float*)d_in[10];
    const float* a0_b   = (const float*)d_in[11];
    const float* ai_w   = (const float*)d_in[12];
    const float* ai_b   = (const float*)d_in[13];
    const float* an_w   = (const float*)d_in[14];
    const float* an_b   = (const float*)d_in[15];
    const float* w_ih   = (const float*)d_in[16];
    const float* w_hh   = (const float*)d_in[17];
    const float* b_ih   = (const float*)d_in[18];
    const float* b_hh   = (const float*)d_in[19];
    const float* fi_w   = (const float*)d_in[20];
    const float* fi_b   = (const float*)d_in[21];
    const float* fn_w   = (const float*)d_in[22];
    const float* fn_b   = (const float*)d_in[23];
    float* out = (float*)d_out;

    prep_kernel<<<(G3 * DRNN + 255) / 256, 256>>>(w_ih, w_hh, fi_w, cnn1_w, cnn_b);

    dim3 gp(108, BL);
    pad_frames_kernel<<<gp, 144>>>(frames);

    dim3 gw(12, 9);
    wc_gemm<<<gw, 256>>>(cnn1_w, cnn_w);

    dim3 gg(M1 / 128, KSPLIT);
    fused_gemm<<<gg, 256>>>();

    bias_bb_kernel<<<49, DCNN>>>(cnn1_b);

    pool_kernel<<<BL, 256>>>(bn_g, bn_b, bn_m, bn_v);
    adapter_kernel<<<BL, DRNN>>>(x, a0_w, a0_b, ai_w, ai_b, an_w, an_b);
    gi_kernel<<<BL / 16, DRNN>>>(b_ih);

    encoder_kernel<<<BATCH, 512>>>(b_hh);
    decoder_kernel<<<BATCH, 512>>>(b_ih, b_hh, fi_b, fn_w, fn_b, out);
}